// round 14
// baseline (speedup 1.0000x reference)
#include <cuda_runtime.h>
#include <cuda_fp16.h>
#include <math.h>
#include <cstdint>

#define S_LEN 2048
#define D_MODEL 1024
#define N_HEADS 16
#define D_KV 64
#define KE 2048              // fp16 limb-plane width [hi1024|lo1024]
#define HSZ (S_LEN * 128)    // per-head Q/K fp16 limb plane ([hi64|lo64])
#define HSZV (S_LEN * 64)

#define QMAX 32385.0f        // int16-range quant ceiling

// ---------------- scratch (__device__ globals; no allocs) -------------------
__device__ float g_bias[N_HEADS * 4096];
__device__ float g_maxs[4];   // 0:X 1:Wq 2:Wk 3:Wv
__device__ __align__(16) __half  g_A2[S_LEN * KE];          // ctx fp16 limbs [s][hi|lo]
__device__ __align__(16) __half  g_Bo[1024 * KE];           // Wo^T fp16 limbs [n][hi|lo], x256
__device__ __align__(16) int8_t  g_A8h[S_LEN * D_MODEL];    // X int8 limbs
__device__ __align__(16) int8_t  g_A8l[S_LEN * D_MODEL];
__device__ __align__(16) int8_t  g_B8h[3072 * D_MODEL];     // Wq,Wk,Wv ^T int8 limbs
__device__ __align__(16) int8_t  g_B8l[3072 * D_MODEL];
__device__ __align__(16) __half  g_Q2[N_HEADS * HSZ];       // [h][s][Qh64|Ql64]
__device__ __align__(16) __half  g_K2[N_HEADS * HSZ];       // [h][s][Kh64|Kl64]
__device__ __align__(16) __half  g_V [N_HEADS * HSZV];      // fp16 single

__device__ __forceinline__ uint32_t smem_u32(const void* p) {
    uint32_t a;
    asm("{ .reg .u64 t; cvta.to.shared.u64 t, %1; cvt.u32.u64 %0, t; }" : "=r"(a) : "l"(p));
    return a;
}

// ---------------- mma / ldmatrix / cp.async primitives ----------------------
__device__ __forceinline__ void ldm_x4(uint32_t* r, uint32_t addr) {
    asm volatile("ldmatrix.sync.aligned.m8n8.x4.shared.b16 {%0,%1,%2,%3}, [%4];"
                 : "=r"(r[0]), "=r"(r[1]), "=r"(r[2]), "=r"(r[3]) : "r"(addr));
}
__device__ __forceinline__ void ldm_x4t(uint32_t* r, uint32_t addr) {
    asm volatile("ldmatrix.sync.aligned.m8n8.x4.trans.shared.b16 {%0,%1,%2,%3}, [%4];"
                 : "=r"(r[0]), "=r"(r[1]), "=r"(r[2]), "=r"(r[3]) : "r"(addr));
}
__device__ __forceinline__ void mma_hf(float* d, const uint32_t* a, const uint32_t* b) {
    asm volatile("mma.sync.aligned.m16n8k16.row.col.f32.f16.f16.f32 "
                 "{%0,%1,%2,%3}, {%4,%5,%6,%7}, {%8,%9}, {%0,%1,%2,%3};"
                 : "+f"(d[0]), "+f"(d[1]), "+f"(d[2]), "+f"(d[3])
                 : "r"(a[0]), "r"(a[1]), "r"(a[2]), "r"(a[3]), "r"(b[0]), "r"(b[1]));
}
__device__ __forceinline__ void mma_s8(int* d, const uint32_t* a, const uint32_t* b) {
    asm volatile("mma.sync.aligned.m16n8k32.row.col.s32.s8.s8.s32 "
                 "{%0,%1,%2,%3}, {%4,%5,%6,%7}, {%8,%9}, {%0,%1,%2,%3};"
                 : "+r"(d[0]), "+r"(d[1]), "+r"(d[2]), "+r"(d[3])
                 : "r"(a[0]), "r"(a[1]), "r"(a[2]), "r"(a[3]), "r"(b[0]), "r"(b[1]));
}
__device__ __forceinline__ void cp16(uint32_t saddr, const void* gaddr) {
    asm volatile("cp.async.cg.shared.global [%0], [%1], 16;" :: "r"(saddr), "l"(gaddr));
}
#define CP_COMMIT() asm volatile("cp.async.commit_group;" ::: "memory")
#define CP_WAIT(n)  asm volatile("cp.async.wait_group %0;" :: "n"(n) : "memory")

__device__ __forceinline__ uint32_t pack_f16(float lo, float hi) {
    uint32_t r;
    asm("cvt.rn.f16x2.f32 %0, %1, %2;" : "=r"(r) : "f"(hi), "f"(lo));
    return r;
}
__device__ __forceinline__ void quant2(float x, float inv_s, int8_t& h, int8_t& l) {
    float xs = x * inv_s;
    xs = fminf(fmaxf(xs, -QMAX), QMAX);
    int x16 = __float2int_rn(xs);
    int a0 = (x16 + 128) >> 8;
    int a1 = x16 - (a0 << 8);
    h = (int8_t)a0; l = (int8_t)a1;
}

// ---------------------------------------------------------------------------
// Bias LUT
// ---------------------------------------------------------------------------
__global__ void bias_kernel(const float* __restrict__ rel_bias) {
    int idx = blockIdx.x * blockDim.x + threadIdx.x;
    if (idx >= N_HEADS * 4095) return;
    int h = idx / 4095;
    int di = idx % 4095;
    int delta = di - 2047;
    int bucket = (delta > 0) ? 16 : 0;
    int rp = abs(delta);
    if (rp < 8) {
        bucket += rp;
    } else {
        float lr = logf((float)rp * 0.125f) / 2.7725887f;
        int large = 8 + (int)(lr * 8.0f);
        bucket += (large < 15) ? large : 15;
    }
    g_bias[h * 4096 + di] = rel_bias[bucket * N_HEADS + h];
}

// ---------------------------------------------------------------------------
// maxabs + quant + conv kernels
// ---------------------------------------------------------------------------
__global__ void max_f32(const float* __restrict__ src, int n, int slot) {
    float v = 0.f;
    for (int i = blockIdx.x * blockDim.x + threadIdx.x; i < n; i += gridDim.x * blockDim.x)
        v = fmaxf(v, fabsf(src[i]));
#pragma unroll
    for (int off = 16; off; off >>= 1)
        v = fmaxf(v, __shfl_xor_sync(0xffffffffu, v, off));
    if ((threadIdx.x & 31) == 0)
        atomicMax((int*)&g_maxs[slot], __float_as_int(v));
}

__global__ void quantX_kernel(const float* __restrict__ X) {
    float inv_s = QMAX / g_maxs[0];
    int i = blockIdx.x * blockDim.x + threadIdx.x;
    quant2(X[i], inv_s, g_A8h[i], g_A8l[i]);
}

// transpose + quantize Wq/Wk/Wv -> g_B8h/l rows z*1024+n
__global__ void quantW_kernel(const float* __restrict__ Wq, const float* __restrict__ Wk,
                              const float* __restrict__ Wv) {
    const float* W = (blockIdx.z == 0) ? Wq : (blockIdx.z == 1) ? Wk : Wv;
    float inv_s = QMAX / g_maxs[1 + blockIdx.z];
    __shared__ float sm[32][33];
    int n0 = blockIdx.x * 32, k0 = blockIdx.y * 32;
    int tx = threadIdx.x, ty = threadIdx.y;
#pragma unroll
    for (int j = 0; j < 4; j++)
        sm[ty + j * 8][tx] = W[(size_t)(k0 + ty + j * 8) * D_MODEL + n0 + tx];
    __syncthreads();
#pragma unroll
    for (int j = 0; j < 4; j++) {
        int n = n0 + ty + j * 8, k = k0 + tx;
        size_t o = (size_t)(blockIdx.z * 1024 + n) * D_MODEL + k;
        quant2(sm[tx][ty + j * 8], inv_s, g_B8h[o], g_B8l[o]);
    }
}

// transpose + split Wo*256 -> g_Bo rows [Bh(1024)|Bl(1024)] fp16
__global__ void convBo_kernel(const float* __restrict__ Wo) {
    __shared__ float sm[32][33];
    int n0 = blockIdx.x * 32, k0 = blockIdx.y * 32;
    int tx = threadIdx.x, ty = threadIdx.y;
#pragma unroll
    for (int j = 0; j < 4; j++)
        sm[ty + j * 8][tx] = Wo[(size_t)(k0 + ty + j * 8) * D_MODEL + n0 + tx];
    __syncthreads();
#pragma unroll
    for (int j = 0; j < 4; j++) {
        int n = n0 + ty + j * 8, k = k0 + tx;
        float v = sm[tx][ty + j * 8] * 256.0f;
        __half h = __float2half_rn(v);
        g_Bo[(size_t)n * KE + k] = h;
        g_Bo[(size_t)n * KE + 1024 + k] = __float2half_rn(v - __half2float(h));
    }
}

// ---------------------------------------------------------------------------
// int8 QKV GEMM: CTA tile 128x64, warp tile 32x32 (8 warps). BK=64, S=3.
// Q,K (n<2048): exact 4-product; V: 3-product. Register-safe (~140 regs).
// ---------------------------------------------------------------------------
#define P8 80
#define TA8 (128 * P8)                    // 10240 B per A limb array
#define TB8 (64 * P8)                     // 5120 B per B limb array
#define S8B (2 * TA8 + 2 * TB8)           // 30720 B per stage

__global__ __launch_bounds__(256, 1) void gemm_i8qkv() {
    extern __shared__ __align__(16) int8_t sm8[];
    const int t = threadIdx.x;
    const int warp = t >> 5, lane = t & 31;
    const int m0 = blockIdx.y * 128, n0 = blockIdx.x * 64;
    const int wm0 = (warp >> 1) * 32;
    const int wn0 = (warp & 1) * 32;
    const bool full = (n0 < 2048);        // Q,K exact 4-product

    const uint32_t sbase = smem_u32(sm8);
    const int lrow = t >> 2, lcol = (t & 3) * 16;

    auto issue_stage = [&](int slot, int kb) {
        uint32_t so = sbase + (uint32_t)slot * S8B;
#pragma unroll
        for (int p = 0; p < 2; p++) {
            int row = lrow + p * 64;
            uint32_t sofs = (uint32_t)row * P8 + lcol;
            size_t ga = (size_t)(m0 + row) * D_MODEL + kb * 64 + lcol;
            cp16(so + sofs,       g_A8h + ga);
            cp16(so + TA8 + sofs, g_A8l + ga);
        }
        {
            size_t gb = (size_t)(n0 + lrow) * D_MODEL + kb * 64 + lcol;
            uint32_t sofs = (uint32_t)lrow * P8 + lcol;
            cp16(so + 2 * TA8 + sofs,       g_B8h + gb);
            cp16(so + 2 * TA8 + TB8 + sofs, g_B8l + gb);
        }
        CP_COMMIT();
    };

    int hh[2][4][4], mid[2][4][4], ll[2][4][4];
#pragma unroll
    for (int i = 0; i < 2; i++)
#pragma unroll
        for (int j = 0; j < 4; j++)
#pragma unroll
            for (int u = 0; u < 4; u++) { hh[i][j][u] = 0; mid[i][j][u] = 0; ll[i][j][u] = 0; }

    const int arow = wm0 + (lane & 15);
    const int acol = (lane >> 4) * 16;
    const int brow = wn0 + (lane >> 4) * 8 + (lane & 7);
    const int bcol = ((lane >> 3) & 1) * 16;

    issue_stage(0, 0);
    issue_stage(1, 1);

    for (int kb = 0; kb < 16; kb++) {
        if (kb + 1 < 16) { CP_WAIT(1); } else { CP_WAIT(0); }
        __syncthreads();
        if (kb + 2 < 16) issue_stage((kb + 2) % 3, kb + 2);
        uint32_t so = sbase + (uint32_t)(kb % 3) * S8B;
#pragma unroll
        for (int ks = 0; ks < 2; ks++) {
            uint32_t ah[2][4], al[2][4];
#pragma unroll
            for (int i = 0; i < 2; i++) {
                uint32_t rb = so + (uint32_t)(arow + i * 16) * P8 + ks * 32 + acol;
                ldm_x4(ah[i], rb);
                ldm_x4(al[i], rb + TA8);
            }
#pragma unroll
            for (int jp = 0; jp < 2; jp++) {
                uint32_t rb = so + 2 * TA8 + (uint32_t)(brow + jp * 16) * P8 + ks * 32 + bcol;
                uint32_t bh4[4], bl4[4];
                ldm_x4(bh4, rb);
                ldm_x4(bl4, rb + TB8);
#pragma unroll
                for (int i = 0; i < 2; i++) {
                    mma_s8(hh[i][2 * jp],      ah[i], bh4 + 0);
                    mma_s8(hh[i][2 * jp + 1],  ah[i], bh4 + 2);
                    mma_s8(mid[i][2 * jp],     ah[i], bl4 + 0);
                    mma_s8(mid[i][2 * jp + 1], ah[i], bl4 + 2);
                    mma_s8(mid[i][2 * jp],     al[i], bh4 + 0);
                    mma_s8(mid[i][2 * jp + 1], al[i], bh4 + 2);
                    if (full) {
                        mma_s8(ll[i][2 * jp],     al[i], bl4 + 0);
                        mma_s8(ll[i][2 * jp + 1], al[i], bl4 + 2);
                    }
                }
            }
        }
    }

    // epilogue: dequant + route (Q/K fp16 limbs, V fp16)
    const float sc = (g_maxs[0] / QMAX) * (g_maxs[1 + (n0 >> 10)] / QMAX);
#pragma unroll
    for (int i = 0; i < 2; i++) {
        int r = m0 + wm0 + i * 16 + (lane >> 2);
#pragma unroll
        for (int j = 0; j < 4; j++) {
            int n = n0 + wn0 + j * 8 + (lane & 3) * 2;
#pragma unroll
            for (int half_ = 0; half_ < 2; half_++) {
                int rr = r + half_ * 8;
                float y0 = sc * fmaf(65536.f, (float)hh[i][j][2 * half_],
                            fmaf(256.f, (float)mid[i][j][2 * half_], (float)ll[i][j][2 * half_]));
                float y1 = sc * fmaf(65536.f, (float)hh[i][j][2 * half_ + 1],
                            fmaf(256.f, (float)mid[i][j][2 * half_ + 1], (float)ll[i][j][2 * half_ + 1]));
                int z = n >> 10, hd = (n >> 6) & 15, dd = n & 63;
                if (z < 2) {
                    __half* q = (z == 0 ? g_Q2 : g_K2) + (size_t)hd * HSZ + (size_t)rr * 128 + dd;
                    __half h0 = __float2half_rn(y0), h1 = __float2half_rn(y1);
                    *(__half2*)q = __halves2half2(h0, h1);
                    *(__half2*)(q + 64) = __halves2half2(
                        __float2half_rn(y0 - __half2float(h0)),
                        __float2half_rn(y1 - __half2float(h1)));
                } else {
                    __half* vv = g_V + (size_t)hd * HSZV + (size_t)rr * 64 + dd;
                    *(__half2*)vv = __halves2half2(__float2half_rn(y0), __float2half_rn(y1));
                }
            }
        }
    }
}

// ---------------------------------------------------------------------------
// fp16 out GEMM (R11 proven, 2-product AhBh+AlBh): out = ctx @ Wo (x256 undone)
// 128x128 tile, BK=32 natural, S=3, 2 CTAs/SM.
// ---------------------------------------------------------------------------
#define PITCH 72
#define TILE_B (128 * PITCH * 2)
#define STAGE_B (2 * TILE_B)

__global__ __launch_bounds__(256, 2) void gemm_out(float* __restrict__ Cout) {
    extern __shared__ __align__(16) __half sm[];
    const int t = threadIdx.x;
    const int warp = t >> 5, lane = t & 31;
    const int m0 = blockIdx.y * 128, n0 = blockIdx.x * 128;
    const int wm0 = (warp >> 1) * 32;
    const int wn0 = (warp & 1) * 64;
    const uint32_t sbase = smem_u32(sm);

    const int lr = t >> 3, lc = (t & 7) * 8;
    const int gcol_off = (lc < 32) ? lc : (lc + 992);

    auto issue_stage = [&](int slot, int kb) {
        uint32_t so = sbase + (uint32_t)slot * STAGE_B;
#pragma unroll
        for (int p = 0; p < 4; p++) {
            int row = lr + p * 32;
            uint32_t sofs = ((uint32_t)row * PITCH + lc) * 2;
            size_t gc = (size_t)kb * 32 + gcol_off;
            cp16(so + sofs,          g_A2 + (size_t)(m0 + row) * KE + gc);
            cp16(so + TILE_B + sofs, g_Bo + (size_t)(n0 + row) * KE + gc);
        }
        CP_COMMIT();
    };

    float d[2][8][4];
#pragma unroll
    for (int i = 0; i < 2; i++)
#pragma unroll
        for (int j = 0; j < 8; j++)
#pragma unroll
            for (int u = 0; u < 4; u++) d[i][j][u] = 0.f;

    const int arow = wm0 + (lane & 15);
    const int acolq = (lane >> 4) * 8;
    const int brow2 = wn0 + (lane >> 4) * 8 + (lane & 7);
    const int bcol2 = ((lane >> 3) & 1) * 8;

    issue_stage(0, 0);
    issue_stage(1, 1);

    for (int kb = 0; kb < 32; kb++) {
        if (kb + 1 < 32) { CP_WAIT(1); } else { CP_WAIT(0); }
        __syncthreads();
        if (kb + 2 < 32) issue_stage((kb + 2) % 3, kb + 2);
        uint32_t so = sbase + (uint32_t)(kb % 3) * STAGE_B;
#pragma unroll
        for (int ks = 0; ks < 2; ks++) {
            uint32_t ah[2][4], al[2][4];
#pragma unroll
            for (int i = 0; i < 2; i++) {
                uint32_t rbase = so + (uint32_t)(arow + i * 16) * PITCH * 2;
                ldm_x4(ah[i], rbase + (ks * 16 + acolq) * 2);
                ldm_x4(al[i], rbase + (32 + ks * 16 + acolq) * 2);
            }
#pragma unroll
            for (int jp = 0; jp < 4; jp++) {
                uint32_t rbase = so + TILE_B + (uint32_t)(brow2 + jp * 16) * PITCH * 2;
                uint32_t bh4[4];
                ldm_x4(bh4, rbase + (ks * 16 + bcol2) * 2);
                mma_hf(d[0][2 * jp],     ah[0], bh4 + 0);
                mma_hf(d[1][2 * jp],     ah[1], bh4 + 0);
                mma_hf(d[0][2 * jp + 1], ah[0], bh4 + 2);
                mma_hf(d[1][2 * jp + 1], ah[1], bh4 + 2);
                mma_hf(d[0][2 * jp],     al[0], bh4 + 0);
                mma_hf(d[1][2 * jp],     al[1], bh4 + 0);
                mma_hf(d[0][2 * jp + 1], al[0], bh4 + 2);
                mma_hf(d[1][2 * jp + 1], al[1], bh4 + 2);
            }
        }
    }

    const float inv256 = 1.0f / 256.0f;
#pragma unroll
    for (int i = 0; i < 2; i++) {
        int r = m0 + wm0 + i * 16 + (lane >> 2);
#pragma unroll
        for (int j = 0; j < 8; j++) {
            int n = n0 + wn0 + j * 8 + (lane & 3) * 2;
            *(float2*)(Cout + (size_t)r * D_MODEL + n) =
                make_float2(d[i][j][0] * inv256, d[i][j][1] * inv256);
            *(float2*)(Cout + (size_t)(r + 8) * D_MODEL + n) =
                make_float2(d[i][j][2] * inv256, d[i][j][3] * inv256);
        }
    }
}

// ---------------------------------------------------------------------------
// fp16 flash attention (R11 proven): QK exact 3-product over [hi64|lo64],
// P fp16, V fp16. 64-key tiles, S=4 stages, QK(i+1) interleaved with PV(i).
// ---------------------------------------------------------------------------
#define APK 136
#define APV 72
#define AK_B (64 * APK * 2)
#define AV_B (64 * APV * 2)
#define AS_B (AK_B + AV_B)
#define AS_N 4

__global__ __launch_bounds__(256, 2) void attn_mma() {
    extern __shared__ __align__(16) char smem[];
    const uint32_t sb = smem_u32(smem);
    const int t = threadIdx.x, w = t >> 5, lane = t & 31;
    const int h = blockIdx.y, q0 = blockIdx.x * 128;

    const __half* Q2 = g_Q2 + (size_t)h * HSZ;
    const __half* K2 = g_K2 + (size_t)h * HSZ;
    const __half* Vp = g_V  + (size_t)h * HSZV;

    {
        int row = t >> 4, colc = (t & 15) * 8;
#pragma unroll
        for (int p = 0; p < 8; p++) {
            int r = row + p * 16;
            cp16(sb + ((uint32_t)r * APK + colc) * 2, Q2 + (size_t)(q0 + r) * 128 + colc);
        }
        CP_COMMIT();
        CP_WAIT(0);
        __syncthreads();
    }
    uint32_t qf[8][4];
    {
        int arow = w * 16 + (lane & 15);
        int acol = (lane >> 4) * 8;
#pragma unroll
        for (int ks = 0; ks < 8; ks++)
            ldm_x4(qf[ks], sb + ((uint32_t)arow * APK + ks * 16 + acol) * 2);
    }
    __syncthreads();

    auto issue_kv = [&](int slot, int i) {
        int k0 = i * 64;
        uint32_t base = sb + (uint32_t)slot * AS_B;
        {
            int row = t >> 4, colc = (t & 15) * 8;
#pragma unroll
            for (int p = 0; p < 4; p++) {
                int r = row + p * 16;
                cp16(base + ((uint32_t)r * APK + colc) * 2, K2 + (size_t)(k0 + r) * 128 + colc);
            }
        }
        {
            int row = t >> 3, colc = (t & 7) * 8;
#pragma unroll
            for (int p = 0; p < 2; p++) {
                int r = row + p * 32;
                cp16(base + AK_B + ((uint32_t)r * APV + colc) * 2, Vp + (size_t)(k0 + r) * 64 + colc);
            }
        }
        CP_COMMIT();
    };

    issue_kv(0, 0);
    issue_kv(1, 1);
    issue_kv(2, 2);

    const int cq = (lane & 3) * 2;
    const int q_r = q0 + w * 16 + (lane >> 2);
    const float* bh = g_bias + h * 4096 + 2047 - q_r;

    const int k_r = (lane >> 4) * 8 + (lane & 7);
    const int k_c = ((lane >> 3) & 1) * 8;
    const int v_r = (lane & 7) + ((lane >> 3) & 1) * 8;
    const int v_c = (lane >> 4) * 8;

    float o[8][4];
#pragma unroll
    for (int j = 0; j < 8; j++)
#pragma unroll
        for (int u = 0; u < 4; u++) o[j][u] = 0.f;
    float m_r = -1e30f, m_r8 = -1e30f, l_r = 0.f, l_r8 = 0.f;
    float s[8][4];

    auto qk_tile = [&](uint32_t stb_k) {
#pragma unroll
        for (int j = 0; j < 8; j++)
#pragma unroll
            for (int u = 0; u < 4; u++) s[j][u] = 0.f;
#pragma unroll
        for (int ks = 0; ks < 4; ks++) {
#pragma unroll
            for (int jp = 0; jp < 4; jp++) {
                uint32_t rbase = stb_k + (uint32_t)((jp * 16 + k_r) * APK) * 2;
                uint32_t kh4[4], kl4[4];
                ldm_x4(kh4, rbase + (ks * 16 + k_c) * 2);
                ldm_x4(kl4, rbase + (64 + ks * 16 + k_c) * 2);
                mma_hf(s[2 * jp],     qf[ks],     kh4 + 0);
                mma_hf(s[2 * jp + 1], qf[ks],     kh4 + 2);
                mma_hf(s[2 * jp],     qf[4 + ks], kh4 + 0);
                mma_hf(s[2 * jp + 1], qf[4 + ks], kh4 + 2);
                mma_hf(s[2 * jp],     qf[ks],     kl4 + 0);
                mma_hf(s[2 * jp + 1], qf[ks],     kl4 + 2);
            }
        }
    };

    CP_WAIT(2);
    __syncthreads();
    qk_tile(sb + 0 * AS_B);

    for (int i = 0; i < 32; i++) {
        const int k0 = i * 64;

        float rmax = -1e30f, rmax8 = -1e30f;
#pragma unroll
        for (int j = 0; j < 8; j++) {
            const float* bp = bh + k0 + j * 8 + cq;
            s[j][0] += __ldg(bp);
            s[j][1] += __ldg(bp + 1);
            s[j][2] += __ldg(bp - 8);
            s[j][3] += __ldg(bp - 7);
            rmax  = fmaxf(rmax,  fmaxf(s[j][0], s[j][1]));
            rmax8 = fmaxf(rmax8, fmaxf(s[j][2], s[j][3]));
        }
#pragma unroll
        for (int off = 1; off <= 2; off <<= 1) {
            rmax  = fmaxf(rmax,  __shfl_xor_sync(0xffffffffu, rmax,  off));
            rmax8 = fmaxf(rmax8, __shfl_xor_sync(0xffffffffu, rmax8, off));
        }
        float mn  = fmaxf(m_r,  rmax);
        float mn8 = fmaxf(m_r8, rmax8);
        float cr  = __expf(m_r - mn);
        float cr8 = __expf(m_r8 - mn8);
        m_r = mn; m_r8 = mn8;
        float sum = 0.f, sum8 = 0.f;
#pragma unroll
        for (int j = 0; j < 8; j++) {
            s[j][0] = __expf(s[j][0] - mn);
            s[j][1] = __expf(s[j][1] - mn);
            s[j][2] = __expf(s[j][2] - mn8);
            s[j][3] = __expf(s[j][3] - mn8);
            sum  += s[j][0] + s[j][1];
            sum8 += s[j][2] + s[j][3];
        }
#pragma unroll
        for (int off = 1; off <= 2; off <<= 1) {
            sum  += __shfl_xor_sync(0xffffffffu, sum,  off);
            sum8 += __shfl_xor_sync(0xffffffffu, sum8, off);
        }
        l_r  = l_r  * cr  + sum;
        l_r8 = l_r8 * cr8 + sum8;
#pragma unroll
        for (int j = 0; j < 8; j++) {
            o[j][0] *= cr;  o[j][1] *= cr;
            o[j][2] *= cr8; o[j][3] *= cr8;
        }
        uint32_t pa[4][4];
#pragma unroll
        for (int ks = 0; ks < 4; ks++) {
            pa[ks][0] = pack_f16(s[2 * ks][0], s[2 * ks][1]);
            pa[ks][1] = pack_f16(s[2 * ks][2], s[2 * ks][3]);
            pa[ks][2] = pack_f16(s[2 * ks + 1][0], s[2 * ks + 1][1]);
            pa[ks][3] = pack_f16(s[2 * ks + 1][2], s[2 * ks + 1][3]);
        }

        const bool not_last = (i + 1 < 32);
        if (not_last) {
            if (i < 30) { CP_WAIT(1); } else { CP_WAIT(0); }
            __syncthreads();
            if (i + 3 < 32) issue_kv((i + 3) & 3, i + 3);
        }

        uint32_t stb_v = sb + (uint32_t)(i & 3) * AS_B;
        if (not_last)
            qk_tile(sb + (uint32_t)((i + 1) & 3) * AS_B);
#pragma unroll
        for (int ks = 0; ks < 4; ks++) {
#pragma unroll
            for (int jp = 0; jp < 4; jp++) {
                uint32_t v4[4];
                ldm_x4t(v4, stb_v + AK_B +
                            ((uint32_t)((ks * 16 + v_r) * APV + jp * 16 + v_c)) * 2);
                mma_hf(o[2 * jp],     pa[ks], v4 + 0);
                mma_hf(o[2 * jp + 1], pa[ks], v4 + 2);
            }
        }
    }

    // epilogue: ctx -> fp16 limb plane g_A2 [s][hi1024|lo1024]
    float ir = 1.f / l_r, ir8 = 1.f / l_r8;
#pragma unroll
    for (int j = 0; j < 8; j++) {
        int col = h * 64 + j * 8 + cq;
#pragma unroll
        for (int half_ = 0; half_ < 2; half_++) {
            int rr = q_r + half_ * 8;
            float scale = half_ ? ir8 : ir;
            float v0 = o[j][2 * half_ + 0] * scale;
            float v1 = o[j][2 * half_ + 1] * scale;
            __half h0 = __float2half_rn(v0), h1 = __float2half_rn(v1);
            __half* dst = g_A2 + (size_t)rr * KE + col;
            *(__half2*)dst = __halves2half2(h0, h1);
            *(__half2*)(dst + 1024) = __halves2half2(
                __float2half_rn(v0 - __half2float(h0)),
                __float2half_rn(v1 - __half2float(h1)));
        }
    }
}

// ---------------------------------------------------------------------------
extern "C" void kernel_launch(void* const* d_in, const int* in_sizes, int n_in,
                              void* d_out, int out_size) {
    const float* X   = (const float*)d_in[0];
    const float* Wq  = (const float*)d_in[1];
    const float* Wk  = (const float*)d_in[2];
    const float* Wv  = (const float*)d_in[3];
    const float* Wo  = (const float*)d_in[4];
    const float* rel = (const float*)d_in[5];
    float* out = (float*)d_out;

    const int qkv_smem = 3 * S8B;         // 92160
    const int out_smem = 3 * STAGE_B;     // 110592
    const int attn_smem = AS_N * AS_B;    // 106496
    cudaFuncSetAttribute(gemm_i8qkv, cudaFuncAttributeMaxDynamicSharedMemorySize, qkv_smem);
    cudaFuncSetAttribute(gemm_out,   cudaFuncAttributeMaxDynamicSharedMemorySize, out_smem);
    cudaFuncSetAttribute(attn_mma,   cudaFuncAttributeMaxDynamicSharedMemorySize, attn_smem);

    bias_kernel<<<(N_HEADS * 4095 + 255) / 256, 256>>>(rel);
    max_f32<<<128, 256>>>(X, S_LEN * D_MODEL, 0);
    max_f32<<<64, 256>>>(Wq, D_MODEL * D_MODEL, 1);
    max_f32<<<64, 256>>>(Wk, D_MODEL * D_MODEL, 2);
    max_f32<<<64, 256>>>(Wv, D_MODEL * D_MODEL, 3);
    quantX_kernel<<<(S_LEN * D_MODEL) / 256, 256>>>(X);
    quantW_kernel<<<dim3(32, 32, 3), dim3(32, 8)>>>(Wq, Wk, Wv);
    convBo_kernel<<<dim3(32, 32), dim3(32, 8)>>>(Wo);
    gemm_i8qkv<<<dim3(48, 16), 256, qkv_smem>>>();
    attn_mma<<<dim3(16, 16), 256, attn_smem>>>();
    gemm_out<<<dim3(8, 16), 256, out_smem>>>(out);
}

// round 15
// speedup vs baseline: 1.0563x; 1.0563x over previous
#include <cuda_runtime.h>
#include <cuda_fp16.h>
#include <math.h>
#include <cstdint>

#define S_LEN 2048
#define D_MODEL 1024
#define N_HEADS 16
#define D_KV 64
#define KE 2048              // fp16 limb-plane width [hi1024|lo1024]
#define HSZ (S_LEN * 128)    // per-head Q/K fp16 limb plane ([hi64|lo64])
#define HSZV (S_LEN * 64)

#define QMAX 32385.0f        // int16-range quant ceiling

// ---------------- scratch (__device__ globals; no allocs) -------------------
__device__ float g_bias[N_HEADS * 4096];
__device__ float g_maxs[4];   // 0:X 1:Wq 2:Wk 3:Wv
__device__ __align__(16) __half  g_A2[S_LEN * KE];          // ctx fp16 limbs [s][hi|lo]
__device__ __align__(16) __half  g_Bo[1024 * KE];           // Wo^T fp16 limbs [n][hi|lo], x256
__device__ __align__(16) int8_t  g_A8h[S_LEN * D_MODEL];    // X int8 limbs
__device__ __align__(16) int8_t  g_A8l[S_LEN * D_MODEL];
__device__ __align__(16) int8_t  g_B8h[3072 * D_MODEL];     // Wq,Wk,Wv ^T int8 limbs
__device__ __align__(16) int8_t  g_B8l[3072 * D_MODEL];
__device__ __align__(16) __half  g_Q2[N_HEADS * HSZ];       // [h][s][Qh64|Ql64]
__device__ __align__(16) __half  g_K2[N_HEADS * HSZ];       // [h][s][Kh64|Kl64]
__device__ __align__(16) __half  g_V [N_HEADS * HSZV];      // fp16 single

__device__ __forceinline__ uint32_t smem_u32(const void* p) {
    uint32_t a;
    asm("{ .reg .u64 t; cvta.to.shared.u64 t, %1; cvt.u32.u64 %0, t; }" : "=r"(a) : "l"(p));
    return a;
}

// ---------------- mma / ldmatrix / cp.async primitives ----------------------
__device__ __forceinline__ void ldm_x4(uint32_t* r, uint32_t addr) {
    asm volatile("ldmatrix.sync.aligned.m8n8.x4.shared.b16 {%0,%1,%2,%3}, [%4];"
                 : "=r"(r[0]), "=r"(r[1]), "=r"(r[2]), "=r"(r[3]) : "r"(addr));
}
__device__ __forceinline__ void ldm_x4t(uint32_t* r, uint32_t addr) {
    asm volatile("ldmatrix.sync.aligned.m8n8.x4.trans.shared.b16 {%0,%1,%2,%3}, [%4];"
                 : "=r"(r[0]), "=r"(r[1]), "=r"(r[2]), "=r"(r[3]) : "r"(addr));
}
__device__ __forceinline__ void mma_hf(float* d, const uint32_t* a, const uint32_t* b) {
    asm volatile("mma.sync.aligned.m16n8k16.row.col.f32.f16.f16.f32 "
                 "{%0,%1,%2,%3}, {%4,%5,%6,%7}, {%8,%9}, {%0,%1,%2,%3};"
                 : "+f"(d[0]), "+f"(d[1]), "+f"(d[2]), "+f"(d[3])
                 : "r"(a[0]), "r"(a[1]), "r"(a[2]), "r"(a[3]), "r"(b[0]), "r"(b[1]));
}
__device__ __forceinline__ void mma_s8(int* d, const uint32_t* a, const uint32_t* b) {
    asm volatile("mma.sync.aligned.m16n8k32.row.col.s32.s8.s8.s32 "
                 "{%0,%1,%2,%3}, {%4,%5,%6,%7}, {%8,%9}, {%0,%1,%2,%3};"
                 : "+r"(d[0]), "+r"(d[1]), "+r"(d[2]), "+r"(d[3])
                 : "r"(a[0]), "r"(a[1]), "r"(a[2]), "r"(a[3]), "r"(b[0]), "r"(b[1]));
}
__device__ __forceinline__ void cp16(uint32_t saddr, const void* gaddr) {
    asm volatile("cp.async.cg.shared.global [%0], [%1], 16;" :: "r"(saddr), "l"(gaddr));
}
#define CP_COMMIT() asm volatile("cp.async.commit_group;" ::: "memory")
#define CP_WAIT(n)  asm volatile("cp.async.wait_group %0;" :: "n"(n) : "memory")

__device__ __forceinline__ uint32_t pack_f16(float lo, float hi) {
    uint32_t r;
    asm("cvt.rn.f16x2.f32 %0, %1, %2;" : "=r"(r) : "f"(hi), "f"(lo));
    return r;
}
__device__ __forceinline__ void quant2(float x, float inv_s, int8_t& h, int8_t& l) {
    float xs = x * inv_s;
    xs = fminf(fmaxf(xs, -QMAX), QMAX);
    int x16 = __float2int_rn(xs);
    int a0 = (x16 + 128) >> 8;
    int a1 = x16 - (a0 << 8);
    h = (int8_t)a0; l = (int8_t)a1;
}

// ---------------------------------------------------------------------------
// Bias LUT
// ---------------------------------------------------------------------------
__global__ void bias_kernel(const float* __restrict__ rel_bias) {
    int idx = blockIdx.x * blockDim.x + threadIdx.x;
    if (idx >= N_HEADS * 4095) return;
    int h = idx / 4095;
    int di = idx % 4095;
    int delta = di - 2047;
    int bucket = (delta > 0) ? 16 : 0;
    int rp = abs(delta);
    if (rp < 8) {
        bucket += rp;
    } else {
        float lr = logf((float)rp * 0.125f) / 2.7725887f;
        int large = 8 + (int)(lr * 8.0f);
        bucket += (large < 15) ? large : 15;
    }
    g_bias[h * 4096 + di] = rel_bias[bucket * N_HEADS + h];
}

// ---------------------------------------------------------------------------
// Fused max-abs over X, Wq, Wk, Wv (one launch, float4, grid-stride)
// ---------------------------------------------------------------------------
__global__ void max4_kernel(const float* __restrict__ X, const float* __restrict__ Wq,
                            const float* __restrict__ Wk, const float* __restrict__ Wv) {
    int slot = blockIdx.y;
    const float* src = (slot == 0) ? X : (slot == 1) ? Wq : (slot == 2) ? Wk : Wv;
    int n4 = ((slot == 0) ? (S_LEN * D_MODEL) : (D_MODEL * D_MODEL)) / 4;
    float v = 0.f;
    for (int i = blockIdx.x * blockDim.x + threadIdx.x; i < n4; i += gridDim.x * blockDim.x) {
        float4 x = ((const float4*)src)[i];
        v = fmaxf(v, fmaxf(fmaxf(fabsf(x.x), fabsf(x.y)), fmaxf(fabsf(x.z), fabsf(x.w))));
    }
#pragma unroll
    for (int off = 16; off; off >>= 1)
        v = fmaxf(v, __shfl_xor_sync(0xffffffffu, v, off));
    if ((threadIdx.x & 31) == 0)
        atomicMax((int*)&g_maxs[slot], __float_as_int(v));
}

// ---------------------------------------------------------------------------
// quant + conv kernels
// ---------------------------------------------------------------------------
__global__ void quantX_kernel(const float* __restrict__ X) {
    float inv_s = QMAX / g_maxs[0];
    int i = (blockIdx.x * blockDim.x + threadIdx.x) * 4;
    float4 x = *(const float4*)(X + i);
    int8_t h[4], l[4];
    quant2(x.x, inv_s, h[0], l[0]);
    quant2(x.y, inv_s, h[1], l[1]);
    quant2(x.z, inv_s, h[2], l[2]);
    quant2(x.w, inv_s, h[3], l[3]);
    *(char4*)(g_A8h + i) = make_char4(h[0], h[1], h[2], h[3]);
    *(char4*)(g_A8l + i) = make_char4(l[0], l[1], l[2], l[3]);
}

// transpose + quantize Wq/Wk/Wv -> g_B8h/l rows z*1024+n
__global__ void quantW_kernel(const float* __restrict__ Wq, const float* __restrict__ Wk,
                              const float* __restrict__ Wv) {
    const float* W = (blockIdx.z == 0) ? Wq : (blockIdx.z == 1) ? Wk : Wv;
    float inv_s = QMAX / g_maxs[1 + blockIdx.z];
    __shared__ float sm[32][33];
    int n0 = blockIdx.x * 32, k0 = blockIdx.y * 32;
    int tx = threadIdx.x, ty = threadIdx.y;
#pragma unroll
    for (int j = 0; j < 4; j++)
        sm[ty + j * 8][tx] = W[(size_t)(k0 + ty + j * 8) * D_MODEL + n0 + tx];
    __syncthreads();
#pragma unroll
    for (int j = 0; j < 4; j++) {
        int n = n0 + ty + j * 8, k = k0 + tx;
        size_t o = (size_t)(blockIdx.z * 1024 + n) * D_MODEL + k;
        quant2(sm[tx][ty + j * 8], inv_s, g_B8h[o], g_B8l[o]);
    }
}

// transpose + split Wo*256 -> g_Bo rows [Bh(1024)|Bl(1024)] fp16
__global__ void convBo_kernel(const float* __restrict__ Wo) {
    __shared__ float sm[32][33];
    int n0 = blockIdx.x * 32, k0 = blockIdx.y * 32;
    int tx = threadIdx.x, ty = threadIdx.y;
#pragma unroll
    for (int j = 0; j < 4; j++)
        sm[ty + j * 8][tx] = Wo[(size_t)(k0 + ty + j * 8) * D_MODEL + n0 + tx];
    __syncthreads();
#pragma unroll
    for (int j = 0; j < 4; j++) {
        int n = n0 + ty + j * 8, k = k0 + tx;
        float v = sm[tx][ty + j * 8] * 256.0f;
        __half h = __float2half_rn(v);
        g_Bo[(size_t)n * KE + k] = h;
        g_Bo[(size_t)n * KE + 1024 + k] = __float2half_rn(v - __half2float(h));
    }
}

// ---------------------------------------------------------------------------
// int8 QKV GEMM (R14 proven): CTA 128x64, warp 32x32, BK=64, S=3.
// Q,K (n<2048): exact 4-product; V: 3-product.
// ---------------------------------------------------------------------------
#define P8 80
#define TA8 (128 * P8)                    // 10240 B per A limb array
#define TB8 (64 * P8)                     // 5120 B per B limb array
#define S8B (2 * TA8 + 2 * TB8)           // 30720 B per stage

__global__ __launch_bounds__(256, 1) void gemm_i8qkv() {
    extern __shared__ __align__(16) int8_t sm8[];
    const int t = threadIdx.x;
    const int warp = t >> 5, lane = t & 31;
    const int m0 = blockIdx.y * 128, n0 = blockIdx.x * 64;
    const int wm0 = (warp >> 1) * 32;
    const int wn0 = (warp & 1) * 32;
    const bool full = (n0 < 2048);        // Q,K exact 4-product

    const uint32_t sbase = smem_u32(sm8);
    const int lrow = t >> 2, lcol = (t & 3) * 16;

    auto issue_stage = [&](int slot, int kb) {
        uint32_t so = sbase + (uint32_t)slot * S8B;
#pragma unroll
        for (int p = 0; p < 2; p++) {
            int row = lrow + p * 64;
            uint32_t sofs = (uint32_t)row * P8 + lcol;
            size_t ga = (size_t)(m0 + row) * D_MODEL + kb * 64 + lcol;
            cp16(so + sofs,       g_A8h + ga);
            cp16(so + TA8 + sofs, g_A8l + ga);
        }
        {
            size_t gb = (size_t)(n0 + lrow) * D_MODEL + kb * 64 + lcol;
            uint32_t sofs = (uint32_t)lrow * P8 + lcol;
            cp16(so + 2 * TA8 + sofs,       g_B8h + gb);
            cp16(so + 2 * TA8 + TB8 + sofs, g_B8l + gb);
        }
        CP_COMMIT();
    };

    int hh[2][4][4], mid[2][4][4], ll[2][4][4];
#pragma unroll
    for (int i = 0; i < 2; i++)
#pragma unroll
        for (int j = 0; j < 4; j++)
#pragma unroll
            for (int u = 0; u < 4; u++) { hh[i][j][u] = 0; mid[i][j][u] = 0; ll[i][j][u] = 0; }

    const int arow = wm0 + (lane & 15);
    const int acol = (lane >> 4) * 16;
    const int brow = wn0 + (lane >> 4) * 8 + (lane & 7);
    const int bcol = ((lane >> 3) & 1) * 16;

    issue_stage(0, 0);
    issue_stage(1, 1);

    for (int kb = 0; kb < 16; kb++) {
        if (kb + 1 < 16) { CP_WAIT(1); } else { CP_WAIT(0); }
        __syncthreads();
        if (kb + 2 < 16) issue_stage((kb + 2) % 3, kb + 2);
        uint32_t so = sbase + (uint32_t)(kb % 3) * S8B;
#pragma unroll
        for (int ks = 0; ks < 2; ks++) {
            uint32_t ah[2][4], al[2][4];
#pragma unroll
            for (int i = 0; i < 2; i++) {
                uint32_t rb = so + (uint32_t)(arow + i * 16) * P8 + ks * 32 + acol;
                ldm_x4(ah[i], rb);
                ldm_x4(al[i], rb + TA8);
            }
#pragma unroll
            for (int jp = 0; jp < 2; jp++) {
                uint32_t rb = so + 2 * TA8 + (uint32_t)(brow + jp * 16) * P8 + ks * 32 + bcol;
                uint32_t bh4[4], bl4[4];
                ldm_x4(bh4, rb);
                ldm_x4(bl4, rb + TB8);
#pragma unroll
                for (int i = 0; i < 2; i++) {
                    mma_s8(hh[i][2 * jp],      ah[i], bh4 + 0);
                    mma_s8(hh[i][2 * jp + 1],  ah[i], bh4 + 2);
                    mma_s8(mid[i][2 * jp],     ah[i], bl4 + 0);
                    mma_s8(mid[i][2 * jp + 1], ah[i], bl4 + 2);
                    mma_s8(mid[i][2 * jp],     al[i], bh4 + 0);
                    mma_s8(mid[i][2 * jp + 1], al[i], bh4 + 2);
                    if (full) {
                        mma_s8(ll[i][2 * jp],     al[i], bl4 + 0);
                        mma_s8(ll[i][2 * jp + 1], al[i], bl4 + 2);
                    }
                }
            }
        }
    }

    // epilogue: dequant + route (Q/K fp16 limbs, V fp16)
    const float sc = (g_maxs[0] / QMAX) * (g_maxs[1 + (n0 >> 10)] / QMAX);
#pragma unroll
    for (int i = 0; i < 2; i++) {
        int r = m0 + wm0 + i * 16 + (lane >> 2);
#pragma unroll
        for (int j = 0; j < 4; j++) {
            int n = n0 + wn0 + j * 8 + (lane & 3) * 2;
#pragma unroll
            for (int half_ = 0; half_ < 2; half_++) {
                int rr = r + half_ * 8;
                float y0 = sc * fmaf(65536.f, (float)hh[i][j][2 * half_],
                            fmaf(256.f, (float)mid[i][j][2 * half_], (float)ll[i][j][2 * half_]));
                float y1 = sc * fmaf(65536.f, (float)hh[i][j][2 * half_ + 1],
                            fmaf(256.f, (float)mid[i][j][2 * half_ + 1], (float)ll[i][j][2 * half_ + 1]));
                int z = n >> 10, hd = (n >> 6) & 15, dd = n & 63;
                if (z < 2) {
                    __half* q = (z == 0 ? g_Q2 : g_K2) + (size_t)hd * HSZ + (size_t)rr * 128 + dd;
                    __half h0 = __float2half_rn(y0), h1 = __float2half_rn(y1);
                    *(__half2*)q = __halves2half2(h0, h1);
                    *(__half2*)(q + 64) = __halves2half2(
                        __float2half_rn(y0 - __half2float(h0)),
                        __float2half_rn(y1 - __half2float(h1)));
                } else {
                    __half* vv = g_V + (size_t)hd * HSZV + (size_t)rr * 64 + dd;
                    *(__half2*)vv = __halves2half2(__float2half_rn(y0), __float2half_rn(y1));
                }
            }
        }
    }
}

// ---------------------------------------------------------------------------
// fp16 out GEMM (proven, 2-product AhBh+AlBh): out = ctx @ Wo (x256 undone)
// ---------------------------------------------------------------------------
#define PITCH 72
#define TILE_B (128 * PITCH * 2)
#define STAGE_B (2 * TILE_B)

__global__ __launch_bounds__(256, 2) void gemm_out(float* __restrict__ Cout) {
    extern __shared__ __align__(16) __half sm[];
    const int t = threadIdx.x;
    const int warp = t >> 5, lane = t & 31;
    const int m0 = blockIdx.y * 128, n0 = blockIdx.x * 128;
    const int wm0 = (warp >> 1) * 32;
    const int wn0 = (warp & 1) * 64;
    const uint32_t sbase = smem_u32(sm);

    const int lr = t >> 3, lc = (t & 7) * 8;
    const int gcol_off = (lc < 32) ? lc : (lc + 992);

    auto issue_stage = [&](int slot, int kb) {
        uint32_t so = sbase + (uint32_t)slot * STAGE_B;
#pragma unroll
        for (int p = 0; p < 4; p++) {
            int row = lr + p * 32;
            uint32_t sofs = ((uint32_t)row * PITCH + lc) * 2;
            size_t gc = (size_t)kb * 32 + gcol_off;
            cp16(so + sofs,          g_A2 + (size_t)(m0 + row) * KE + gc);
            cp16(so + TILE_B + sofs, g_Bo + (size_t)(n0 + row) * KE + gc);
        }
        CP_COMMIT();
    };

    float d[2][8][4];
#pragma unroll
    for (int i = 0; i < 2; i++)
#pragma unroll
        for (int j = 0; j < 8; j++)
#pragma unroll
            for (int u = 0; u < 4; u++) d[i][j][u] = 0.f;

    const int arow = wm0 + (lane & 15);
    const int acolq = (lane >> 4) * 8;
    const int brow2 = wn0 + (lane >> 4) * 8 + (lane & 7);
    const int bcol2 = ((lane >> 3) & 1) * 8;

    issue_stage(0, 0);
    issue_stage(1, 1);

    for (int kb = 0; kb < 32; kb++) {
        if (kb + 1 < 32) { CP_WAIT(1); } else { CP_WAIT(0); }
        __syncthreads();
        if (kb + 2 < 32) issue_stage((kb + 2) % 3, kb + 2);
        uint32_t so = sbase + (uint32_t)(kb % 3) * STAGE_B;
#pragma unroll
        for (int ks = 0; ks < 2; ks++) {
            uint32_t ah[2][4], al[2][4];
#pragma unroll
            for (int i = 0; i < 2; i++) {
                uint32_t rbase = so + (uint32_t)(arow + i * 16) * PITCH * 2;
                ldm_x4(ah[i], rbase + (ks * 16 + acolq) * 2);
                ldm_x4(al[i], rbase + (32 + ks * 16 + acolq) * 2);
            }
#pragma unroll
            for (int jp = 0; jp < 4; jp++) {
                uint32_t rbase = so + TILE_B + (uint32_t)(brow2 + jp * 16) * PITCH * 2;
                uint32_t bh4[4];
                ldm_x4(bh4, rbase + (ks * 16 + bcol2) * 2);
                mma_hf(d[0][2 * jp],     ah[0], bh4 + 0);
                mma_hf(d[1][2 * jp],     ah[1], bh4 + 0);
                mma_hf(d[0][2 * jp + 1], ah[0], bh4 + 2);
                mma_hf(d[1][2 * jp + 1], ah[1], bh4 + 2);
                mma_hf(d[0][2 * jp],     al[0], bh4 + 0);
                mma_hf(d[1][2 * jp],     al[1], bh4 + 0);
                mma_hf(d[0][2 * jp + 1], al[0], bh4 + 2);
                mma_hf(d[1][2 * jp + 1], al[1], bh4 + 2);
            }
        }
    }

    const float inv256 = 1.0f / 256.0f;
#pragma unroll
    for (int i = 0; i < 2; i++) {
        int r = m0 + wm0 + i * 16 + (lane >> 2);
#pragma unroll
        for (int j = 0; j < 8; j++) {
            int n = n0 + wn0 + j * 8 + (lane & 3) * 2;
            *(float2*)(Cout + (size_t)r * D_MODEL + n) =
                make_float2(d[i][j][0] * inv256, d[i][j][1] * inv256);
            *(float2*)(Cout + (size_t)(r + 8) * D_MODEL + n) =
                make_float2(d[i][j][2] * inv256, d[i][j][3] * inv256);
        }
    }
}

// ---------------------------------------------------------------------------
// fp16 flash attention (proven): QK exact 3-product over [hi64|lo64],
// P fp16, V fp16. 64-key tiles, S=4 stages, QK(i+1) interleaved with PV(i).
// ---------------------------------------------------------------------------
#define APK 136
#define APV 72
#define AK_B (64 * APK * 2)
#define AV_B (64 * APV * 2)
#define AS_B (AK_B + AV_B)
#define AS_N 4

__global__ __launch_bounds__(256, 2) void attn_mma() {
    extern __shared__ __align__(16) char smem[];
    const uint32_t sb = smem_u32(smem);
    const int t = threadIdx.x, w = t >> 5, lane = t & 31;
    const int h = blockIdx.y, q0 = blockIdx.x * 128;

    const __half* Q2 = g_Q2 + (size_t)h * HSZ;
    const __half* K2 = g_K2 + (size_t)h * HSZ;
    const __half* Vp = g_V  + (size_t)h * HSZV;

    {
        int row = t >> 4, colc = (t & 15) * 8;
#pragma unroll
        for (int p = 0; p < 8; p++) {
            int r = row + p * 16;
            cp16(sb + ((uint32_t)r * APK + colc) * 2, Q2 + (size_t)(q0 + r) * 128 + colc);
        }
        CP_COMMIT();
        CP_WAIT(0);
        __syncthreads();
    }
    uint32_t qf[8][4];
    {
        int arow = w * 16 + (lane & 15);
        int acol = (lane >> 4) * 8;
#pragma unroll
        for (int ks = 0; ks < 8; ks++)
            ldm_x4(qf[ks], sb + ((uint32_t)arow * APK + ks * 16 + acol) * 2);
    }
    __syncthreads();

    auto issue_kv = [&](int slot, int i) {
        int k0 = i * 64;
        uint32_t base = sb + (uint32_t)slot * AS_B;
        {
            int row = t >> 4, colc = (t & 15) * 8;
#pragma unroll
            for (int p = 0; p < 4; p++) {
                int r = row + p * 16;
                cp16(base + ((uint32_t)r * APK + colc) * 2, K2 + (size_t)(k0 + r) * 128 + colc);
            }
        }
        {
            int row = t >> 3, colc = (t & 7) * 8;
#pragma unroll
            for (int p = 0; p < 2; p++) {
                int r = row + p * 32;
                cp16(base + AK_B + ((uint32_t)r * APV + colc) * 2, Vp + (size_t)(k0 + r) * 64 + colc);
            }
        }
        CP_COMMIT();
    };

    issue_kv(0, 0);
    issue_kv(1, 1);
    issue_kv(2, 2);

    const int cq = (lane & 3) * 2;
    const int q_r = q0 + w * 16 + (lane >> 2);
    const float* bh = g_bias + h * 4096 + 2047 - q_r;

    const int k_r = (lane >> 4) * 8 + (lane & 7);
    const int k_c = ((lane >> 3) & 1) * 8;
    const int v_r = (lane & 7) + ((lane >> 3) & 1) * 8;
    const int v_c = (lane >> 4) * 8;

    float o[8][4];
#pragma unroll
    for (int j = 0; j < 8; j++)
#pragma unroll
        for (int u = 0; u < 4; u++) o[j][u] = 0.f;
    float m_r = -1e30f, m_r8 = -1e30f, l_r = 0.f, l_r8 = 0.f;
    float s[8][4];

    auto qk_tile = [&](uint32_t stb_k) {
#pragma unroll
        for (int j = 0; j < 8; j++)
#pragma unroll
            for (int u = 0; u < 4; u++) s[j][u] = 0.f;
#pragma unroll
        for (int ks = 0; ks < 4; ks++) {
#pragma unroll
            for (int jp = 0; jp < 4; jp++) {
                uint32_t rbase = stb_k + (uint32_t)((jp * 16 + k_r) * APK) * 2;
                uint32_t kh4[4], kl4[4];
                ldm_x4(kh4, rbase + (ks * 16 + k_c) * 2);
                ldm_x4(kl4, rbase + (64 + ks * 16 + k_c) * 2);
                mma_hf(s[2 * jp],     qf[ks],     kh4 + 0);
                mma_hf(s[2 * jp + 1], qf[ks],     kh4 + 2);
                mma_hf(s[2 * jp],     qf[4 + ks], kh4 + 0);
                mma_hf(s[2 * jp + 1], qf[4 + ks], kh4 + 2);
                mma_hf(s[2 * jp],     qf[ks],     kl4 + 0);
                mma_hf(s[2 * jp + 1], qf[ks],     kl4 + 2);
            }
        }
    };

    CP_WAIT(2);
    __syncthreads();
    qk_tile(sb + 0 * AS_B);

    for (int i = 0; i < 32; i++) {
        const int k0 = i * 64;

        float rmax = -1e30f, rmax8 = -1e30f;
#pragma unroll
        for (int j = 0; j < 8; j++) {
            const float* bp = bh + k0 + j * 8 + cq;
            s[j][0] += __ldg(bp);
            s[j][1] += __ldg(bp + 1);
            s[j][2] += __ldg(bp - 8);
            s[j][3] += __ldg(bp - 7);
            rmax  = fmaxf(rmax,  fmaxf(s[j][0], s[j][1]));
            rmax8 = fmaxf(rmax8, fmaxf(s[j][2], s[j][3]));
        }
#pragma unroll
        for (int off = 1; off <= 2; off <<= 1) {
            rmax  = fmaxf(rmax,  __shfl_xor_sync(0xffffffffu, rmax,  off));
            rmax8 = fmaxf(rmax8, __shfl_xor_sync(0xffffffffu, rmax8, off));
        }
        float mn  = fmaxf(m_r,  rmax);
        float mn8 = fmaxf(m_r8, rmax8);
        float cr  = __expf(m_r - mn);
        float cr8 = __expf(m_r8 - mn8);
        m_r = mn; m_r8 = mn8;
        float sum = 0.f, sum8 = 0.f;
#pragma unroll
        for (int j = 0; j < 8; j++) {
            s[j][0] = __expf(s[j][0] - mn);
            s[j][1] = __expf(s[j][1] - mn);
            s[j][2] = __expf(s[j][2] - mn8);
            s[j][3] = __expf(s[j][3] - mn8);
            sum  += s[j][0] + s[j][1];
            sum8 += s[j][2] + s[j][3];
        }
#pragma unroll
        for (int off = 1; off <= 2; off <<= 1) {
            sum  += __shfl_xor_sync(0xffffffffu, sum,  off);
            sum8 += __shfl_xor_sync(0xffffffffu, sum8, off);
        }
        l_r  = l_r  * cr  + sum;
        l_r8 = l_r8 * cr8 + sum8;
#pragma unroll
        for (int j = 0; j < 8; j++) {
            o[j][0] *= cr;  o[j][1] *= cr;
            o[j][2] *= cr8; o[j][3] *= cr8;
        }
        uint32_t pa[4][4];
#pragma unroll
        for (int ks = 0; ks < 4; ks++) {
            pa[ks][0] = pack_f16(s[2 * ks][0], s[2 * ks][1]);
            pa[ks][1] = pack_f16(s[2 * ks][2], s[2 * ks][3]);
            pa[ks][2] = pack_f16(s[2 * ks + 1][0], s[2 * ks + 1][1]);
            pa[ks][3] = pack_f16(s[2 * ks + 1][2], s[2 * ks + 1][3]);
        }

        const bool not_last = (i + 1 < 32);
        if (not_last) {
            if (i < 30) { CP_WAIT(1); } else { CP_WAIT(0); }
            __syncthreads();
            if (i + 3 < 32) issue_kv((i + 3) & 3, i + 3);
        }

        uint32_t stb_v = sb + (uint32_t)(i & 3) * AS_B;
        if (not_last)
            qk_tile(sb + (uint32_t)((i + 1) & 3) * AS_B);
#pragma unroll
        for (int ks = 0; ks < 4; ks++) {
#pragma unroll
            for (int jp = 0; jp < 4; jp++) {
                uint32_t v4[4];
                ldm_x4t(v4, stb_v + AK_B +
                            ((uint32_t)((ks * 16 + v_r) * APV + jp * 16 + v_c)) * 2);
                mma_hf(o[2 * jp],     pa[ks], v4 + 0);
                mma_hf(o[2 * jp + 1], pa[ks], v4 + 2);
            }
        }
    }

    // epilogue: ctx -> fp16 limb plane g_A2 [s][hi1024|lo1024]
    float ir = 1.f / l_r, ir8 = 1.f / l_r8;
#pragma unroll
    for (int j = 0; j < 8; j++) {
        int col = h * 64 + j * 8 + cq;
#pragma unroll
        for (int half_ = 0; half_ < 2; half_++) {
            int rr = q_r + half_ * 8;
            float scale = half_ ? ir8 : ir;
            float v0 = o[j][2 * half_ + 0] * scale;
            float v1 = o[j][2 * half_ + 1] * scale;
            __half h0 = __float2half_rn(v0), h1 = __float2half_rn(v1);
            __half* dst = g_A2 + (size_t)rr * KE + col;
            *(__half2*)dst = __halves2half2(h0, h1);
            *(__half2*)(dst + 1024) = __halves2half2(
                __float2half_rn(v0 - __half2float(h0)),
                __float2half_rn(v1 - __half2float(h1)));
        }
    }
}

// ---------------------------------------------------------------------------
extern "C" void kernel_launch(void* const* d_in, const int* in_sizes, int n_in,
                              void* d_out, int out_size) {
    const float* X   = (const float*)d_in[0];
    const float* Wq  = (const float*)d_in[1];
    const float* Wk  = (const float*)d_in[2];
    const float* Wv  = (const float*)d_in[3];
    const float* Wo  = (const float*)d_in[4];
    const float* rel = (const float*)d_in[5];
    float* out = (float*)d_out;

    const int qkv_smem = 3 * S8B;         // 92160
    const int out_smem = 3 * STAGE_B;     // 110592
    const int attn_smem = AS_N * AS_B;    // 106496
    cudaFuncSetAttribute(gemm_i8qkv, cudaFuncAttributeMaxDynamicSharedMemorySize, qkv_smem);
    cudaFuncSetAttribute(gemm_out,   cudaFuncAttributeMaxDynamicSharedMemorySize, out_smem);
    cudaFuncSetAttribute(attn_mma,   cudaFuncAttributeMaxDynamicSharedMemorySize, attn_smem);

    bias_kernel<<<(N_HEADS * 4095 + 255) / 256, 256>>>(rel);
    max4_kernel<<<dim3(96, 4), 256>>>(X, Wq, Wk, Wv);
    quantX_kernel<<<(S_LEN * D_MODEL / 4) / 256, 256>>>(X);
    quantW_kernel<<<dim3(32, 32, 3), dim3(32, 8)>>>(Wq, Wk, Wv);
    convBo_kernel<<<dim3(32, 32), dim3(32, 8)>>>(Wo);
    gemm_i8qkv<<<dim3(48, 16), 256, qkv_smem>>>();
    attn_mma<<<dim3(16, 16), 256, attn_smem>>>();
    gemm_out<<<dim3(8, 16), 256, out_smem>>>(out);
}

// round 16
// speedup vs baseline: 2.0963x; 1.9846x over previous
#include <cuda_runtime.h>
#include <cuda_fp16.h>
#include <math.h>
#include <cstdint>

#define S_LEN 2048
#define D_MODEL 1024
#define N_HEADS 16
#define D_KV 64
#define KE 2048              // A'/B' width: [hi(1024) | lo(1024)]
#define HSZ (S_LEN * 128)    // per-head Q/K fp16 limb plane ([hi64|lo64])
#define HSZV (S_LEN * 64)

// ---------------- scratch (__device__ globals; no allocs) -------------------
__device__ float g_bias[N_HEADS * 4096];
__device__ __align__(16) __half g_A2[S_LEN * KE];        // X limbs, later ctx limbs
__device__ __align__(16) __half g_B2[4096 * KE];         // W^T limbs [Bh|Bl], x256 (0..3071 qkv, 3072.. Wo)
__device__ __align__(16) __half g_Q2[N_HEADS * HSZ];     // [h][s][Qh64|Ql64]
__device__ __align__(16) __half g_K2[N_HEADS * HSZ];     // [h][s][Kh64|Kl64]
__device__ __align__(16) __half g_V [N_HEADS * HSZV];    // fp16 single

__device__ __forceinline__ uint32_t smem_u32(const void* p) {
    uint32_t a;
    asm("{ .reg .u64 t; cvta.to.shared.u64 t, %1; cvt.u32.u64 %0, t; }" : "=r"(a) : "l"(p));
    return a;
}

// ---------------- mma / ldmatrix / cp.async primitives ----------------------
__device__ __forceinline__ void ldm_x4(uint32_t* r, uint32_t addr) {
    asm volatile("ldmatrix.sync.aligned.m8n8.x4.shared.b16 {%0,%1,%2,%3}, [%4];"
                 : "=r"(r[0]), "=r"(r[1]), "=r"(r[2]), "=r"(r[3]) : "r"(addr));
}
__device__ __forceinline__ void ldm_x4t(uint32_t* r, uint32_t addr) {
    asm volatile("ldmatrix.sync.aligned.m8n8.x4.trans.shared.b16 {%0,%1,%2,%3}, [%4];"
                 : "=r"(r[0]), "=r"(r[1]), "=r"(r[2]), "=r"(r[3]) : "r"(addr));
}
// f32-accumulator fp16 mma
__device__ __forceinline__ void mma_hf(float* d, const uint32_t* a, const uint32_t* b) {
    asm volatile("mma.sync.aligned.m16n8k16.row.col.f32.f16.f16.f32 "
                 "{%0,%1,%2,%3}, {%4,%5,%6,%7}, {%8,%9}, {%0,%1,%2,%3};"
                 : "+f"(d[0]), "+f"(d[1]), "+f"(d[2]), "+f"(d[3])
                 : "r"(a[0]), "r"(a[1]), "r"(a[2]), "r"(a[3]), "r"(b[0]), "r"(b[1]));
}
// f16-accumulator fp16 mma (possible 2x rate) — for small correction terms
__device__ __forceinline__ void mma_h2(uint32_t* d, const uint32_t* a, const uint32_t* b) {
    asm volatile("mma.sync.aligned.m16n8k16.row.col.f16.f16.f16.f16 "
                 "{%0,%1}, {%2,%3,%4,%5}, {%6,%7}, {%0,%1};"
                 : "+r"(d[0]), "+r"(d[1])
                 : "r"(a[0]), "r"(a[1]), "r"(a[2]), "r"(a[3]), "r"(b[0]), "r"(b[1]));
}
__device__ __forceinline__ void cp16(uint32_t saddr, const void* gaddr) {
    asm volatile("cp.async.cg.shared.global [%0], [%1], 16;" :: "r"(saddr), "l"(gaddr));
}
#define CP_COMMIT() asm volatile("cp.async.commit_group;" ::: "memory")
#define CP_WAIT(n)  asm volatile("cp.async.wait_group %0;" :: "n"(n) : "memory")

__device__ __forceinline__ uint32_t pack_f16(float lo, float hi) {
    uint32_t r;
    asm("cvt.rn.f16x2.f32 %0, %1, %2;" : "=r"(r) : "f"(hi), "f"(lo));
    return r;
}
__device__ __forceinline__ float2 unpack_h2(uint32_t v) {
    return __half22float2(*(__half2*)&v);
}

// ---------------------------------------------------------------------------
// Bias LUT
// ---------------------------------------------------------------------------
__global__ void bias_kernel(const float* __restrict__ rel_bias) {
    int idx = blockIdx.x * blockDim.x + threadIdx.x;
    if (idx >= N_HEADS * 4095) return;
    int h = idx / 4095;
    int di = idx % 4095;
    int delta = di - 2047;
    int bucket = (delta > 0) ? 16 : 0;
    int rp = abs(delta);
    if (rp < 8) {
        bucket += rp;
    } else {
        float lr = logf((float)rp * 0.125f) / 2.7725887f;
        int large = 8 + (int)(lr * 8.0f);
        bucket += (large < 15) ? large : 15;
    }
    g_bias[h * 4096 + di] = rel_bias[bucket * N_HEADS + h];
}

// ---------------------------------------------------------------------------
// Converters: fp32 -> fp16 hi/lo limb planes
// ---------------------------------------------------------------------------
__global__ void convA_kernel(const float* __restrict__ X) {
    int i = (blockIdx.x * blockDim.x + threadIdx.x) * 4;
    int row = i >> 10, col = i & 1023;
    float4 v = *(const float4*)(X + i);
    float x[4] = {v.x, v.y, v.z, v.w};
    __half hi[4], lo[4];
#pragma unroll
    for (int u = 0; u < 4; u++) {
        hi[u] = __float2half_rn(x[u]);
        lo[u] = __float2half_rn(x[u] - __half2float(hi[u]));
    }
    __half* dst = g_A2 + (size_t)row * KE + col;
    *(__half2*)(dst + 0) = __halves2half2(hi[0], hi[1]);
    *(__half2*)(dst + 2) = __halves2half2(hi[2], hi[3]);
    *(__half2*)(dst + 1024) = __halves2half2(lo[0], lo[1]);
    *(__half2*)(dst + 1026) = __halves2half2(lo[2], lo[3]);
}

// Transpose + split W*256 into g_B2 rows [Bh|Bl]; z: 0=Wq 1=Wk 2=Wv 3=Wo
__global__ void convB_kernel(const float* __restrict__ Wq, const float* __restrict__ Wk,
                             const float* __restrict__ Wv, const float* __restrict__ Wo) {
    const float* W = (blockIdx.z == 0) ? Wq : (blockIdx.z == 1) ? Wk
                   : (blockIdx.z == 2) ? Wv : Wo;
    __shared__ float sm[32][33];
    int n0 = blockIdx.x * 32, k0 = blockIdx.y * 32;
    int tx = threadIdx.x, ty = threadIdx.y;
#pragma unroll
    for (int j = 0; j < 4; j++)
        sm[ty + j * 8][tx] = W[(size_t)(k0 + ty + j * 8) * D_MODEL + n0 + tx];
    __syncthreads();
#pragma unroll
    for (int j = 0; j < 4; j++) {
        int n = n0 + ty + j * 8, k = k0 + tx;
        float v = sm[tx][ty + j * 8] * 256.0f;
        __half h = __float2half_rn(v);
        size_t o = (size_t)(blockIdx.z * 1024 + n) * KE + k;
        g_B2[o] = h;
        g_B2[o + 1024] = __float2half_rn(v - __half2float(h));
    }
}

// ---------------------------------------------------------------------------
// fp16 GEMM, hi/lo split with f16-acc corrections:
//   C = AhBh (f32 acc)  +  AlBh [+ AhBl if full] (f16 acc)
// 128x128 tile, BK=32 natural, S=3, one sync per kb.
// ---------------------------------------------------------------------------
#define PITCH 72
#define TILE_B (128 * PITCH * 2)
#define STAGE_B (2 * TILE_B)

template <bool QKV>
__global__ __launch_bounds__(256) void gemm_mma(float* __restrict__ Cout) {
    extern __shared__ __align__(16) __half sm[];
    const int t = threadIdx.x;
    const int warp = t >> 5, lane = t & 31;
    const int m0 = blockIdx.y * 128, n0 = blockIdx.x * 128;
    const int wm0 = (warp >> 1) * 32;
    const int wn0 = (warp & 1) * 64;
    const bool full = QKV && (blockIdx.x < 16);    // Q,K exact 3-product

    const __half* Bbase = g_B2 + (QKV ? 0 : (size_t)3072 * KE);
    const uint32_t sbase = smem_u32(sm);

    const int lr = t >> 3, lc = (t & 7) * 8;
    const int gcol_off = (lc < 32) ? lc : (lc + 992);   // hi strip | lo strip

    auto issue_stage = [&](int slot, int kb) {
        uint32_t so = sbase + (uint32_t)slot * STAGE_B;
#pragma unroll
        for (int p = 0; p < 4; p++) {
            int row = lr + p * 32;
            uint32_t sofs = ((uint32_t)row * PITCH + lc) * 2;
            size_t gc = (size_t)kb * 32 + gcol_off;
            cp16(so + sofs,          g_A2 + (size_t)(m0 + row) * KE + gc);
            cp16(so + TILE_B + sofs, Bbase + (size_t)(n0 + row) * KE + gc);
        }
        CP_COMMIT();
    };

    float d[2][8][4];
    uint32_t cc[2][8][2];
#pragma unroll
    for (int i = 0; i < 2; i++)
#pragma unroll
        for (int j = 0; j < 8; j++) {
#pragma unroll
            for (int u = 0; u < 4; u++) d[i][j][u] = 0.f;
            cc[i][j][0] = 0u; cc[i][j][1] = 0u;
        }

    const int arow = wm0 + (lane & 15);
    const int acolq = (lane >> 4) * 8;
    const int brow2 = wn0 + (lane >> 4) * 8 + (lane & 7);
    const int bcol2 = ((lane >> 3) & 1) * 8;

    issue_stage(0, 0);
    issue_stage(1, 1);

    for (int kb = 0; kb < 32; kb++) {
        if (kb + 1 < 32) { CP_WAIT(1); } else { CP_WAIT(0); }
        __syncthreads();
        if (kb + 2 < 32) issue_stage((kb + 2) % 3, kb + 2);
        uint32_t so = sbase + (uint32_t)(kb % 3) * STAGE_B;
#pragma unroll
        for (int ks = 0; ks < 2; ks++) {
            uint32_t ah[2][4], al[2][4];
#pragma unroll
            for (int i = 0; i < 2; i++) {
                uint32_t rbase = so + (uint32_t)(arow + i * 16) * PITCH * 2;
                ldm_x4(ah[i], rbase + (ks * 16 + acolq) * 2);
                ldm_x4(al[i], rbase + (32 + ks * 16 + acolq) * 2);
            }
#pragma unroll
            for (int jp = 0; jp < 4; jp++) {
                uint32_t rbase = so + TILE_B + (uint32_t)(brow2 + jp * 16) * PITCH * 2;
                uint32_t bh4[4];
                ldm_x4(bh4, rbase + (ks * 16 + bcol2) * 2);
                // main product: f32 accumulators
                mma_hf(d[0][2 * jp],     ah[0], bh4 + 0);
                mma_hf(d[1][2 * jp],     ah[1], bh4 + 0);
                mma_hf(d[0][2 * jp + 1], ah[0], bh4 + 2);
                mma_hf(d[1][2 * jp + 1], ah[1], bh4 + 2);
                // corrections: f16 accumulators
                mma_h2(cc[0][2 * jp],     al[0], bh4 + 0);
                mma_h2(cc[1][2 * jp],     al[1], bh4 + 0);
                mma_h2(cc[0][2 * jp + 1], al[0], bh4 + 2);
                mma_h2(cc[1][2 * jp + 1], al[1], bh4 + 2);
                if (full) {
                    uint32_t bl4[4];
                    ldm_x4(bl4, rbase + (32 + ks * 16 + bcol2) * 2);
                    mma_h2(cc[0][2 * jp],     ah[0], bl4 + 0);
                    mma_h2(cc[1][2 * jp],     ah[1], bl4 + 0);
                    mma_h2(cc[0][2 * jp + 1], ah[0], bl4 + 2);
                    mma_h2(cc[1][2 * jp + 1], ah[1], bl4 + 2);
                }
            }
        }
    }

    // epilogue (x256 W scaling undone)
    const float inv256 = 1.0f / 256.0f;
#pragma unroll
    for (int i = 0; i < 2; i++) {
        int r = m0 + wm0 + i * 16 + (lane >> 2);
#pragma unroll
        for (int j = 0; j < 8; j++) {
            int n = n0 + wn0 + j * 8 + (lane & 3) * 2;
            float2 c01 = unpack_h2(cc[i][j][0]);
            float2 c23 = unpack_h2(cc[i][j][1]);
            float y[4] = {(d[i][j][0] + c01.x) * inv256, (d[i][j][1] + c01.y) * inv256,
                          (d[i][j][2] + c23.x) * inv256, (d[i][j][3] + c23.y) * inv256};
#pragma unroll
            for (int half_ = 0; half_ < 2; half_++) {
                int rr = r + half_ * 8;
                float v0 = y[2 * half_], v1 = y[2 * half_ + 1];
                if (QKV) {
                    int z = n >> 10, hd = (n >> 6) & 15, dd = n & 63;
                    if (z < 2) {
                        __half* q = (z == 0 ? g_Q2 : g_K2) + (size_t)hd * HSZ + (size_t)rr * 128 + dd;
                        __half h0 = __float2half_rn(v0), h1 = __float2half_rn(v1);
                        *(__half2*)q = __halves2half2(h0, h1);
                        *(__half2*)(q + 64) = __halves2half2(
                            __float2half_rn(v0 - __half2float(h0)),
                            __float2half_rn(v1 - __half2float(h1)));
                    } else {
                        __half* vv = g_V + (size_t)hd * HSZV + (size_t)rr * 64 + dd;
                        *(__half2*)vv = __halves2half2(__float2half_rn(v0), __float2half_rn(v1));
                    }
                } else {
                    *(float2*)(Cout + (size_t)rr * D_MODEL + n) = make_float2(v0, v1);
                }
            }
        }
    }
}

// ---------------------------------------------------------------------------
// fp16 flash attention: S = QhKh (f32 acc) + QlKh + QhKl (f16 acc).
// P fp16, V fp16 f32-acc. 64-key tiles, S=4 stages, QK(i+1) || PV(i).
// ---------------------------------------------------------------------------
#define APK 136
#define APV 72
#define AK_B (64 * APK * 2)
#define AV_B (64 * APV * 2)
#define AS_B (AK_B + AV_B)
#define AS_N 4

__global__ __launch_bounds__(256) void attn_mma() {
    extern __shared__ __align__(16) char smem[];
    const uint32_t sb = smem_u32(smem);
    const int t = threadIdx.x, w = t >> 5, lane = t & 31;
    const int h = blockIdx.y, q0 = blockIdx.x * 128;

    const __half* Q2 = g_Q2 + (size_t)h * HSZ;
    const __half* K2 = g_K2 + (size_t)h * HSZ;
    const __half* Vp = g_V  + (size_t)h * HSZV;

    {
        int row = t >> 4, colc = (t & 15) * 8;
#pragma unroll
        for (int p = 0; p < 8; p++) {
            int r = row + p * 16;
            cp16(sb + ((uint32_t)r * APK + colc) * 2, Q2 + (size_t)(q0 + r) * 128 + colc);
        }
        CP_COMMIT();
        CP_WAIT(0);
        __syncthreads();
    }
    uint32_t qf[8][4];   // ks 0-3: Qh, ks 4-7: Ql
    {
        int arow = w * 16 + (lane & 15);
        int acol = (lane >> 4) * 8;
#pragma unroll
        for (int ks = 0; ks < 8; ks++)
            ldm_x4(qf[ks], sb + ((uint32_t)arow * APK + ks * 16 + acol) * 2);
    }
    __syncthreads();

    auto issue_kv = [&](int slot, int i) {
        int k0 = i * 64;
        uint32_t base = sb + (uint32_t)slot * AS_B;
        {
            int row = t >> 4, colc = (t & 15) * 8;
#pragma unroll
            for (int p = 0; p < 4; p++) {
                int r = row + p * 16;
                cp16(base + ((uint32_t)r * APK + colc) * 2, K2 + (size_t)(k0 + r) * 128 + colc);
            }
        }
        {
            int row = t >> 3, colc = (t & 7) * 8;
#pragma unroll
            for (int p = 0; p < 2; p++) {
                int r = row + p * 32;
                cp16(base + AK_B + ((uint32_t)r * APV + colc) * 2, Vp + (size_t)(k0 + r) * 64 + colc);
            }
        }
        CP_COMMIT();
    };

    issue_kv(0, 0);
    issue_kv(1, 1);
    issue_kv(2, 2);

    const int cq = (lane & 3) * 2;
    const int q_r = q0 + w * 16 + (lane >> 2);
    const float* bh = g_bias + h * 4096 + 2047 - q_r;

    const int k_r = (lane >> 4) * 8 + (lane & 7);
    const int k_c = ((lane >> 3) & 1) * 8;
    const int v_r = (lane & 7) + ((lane >> 3) & 1) * 8;
    const int v_c = (lane >> 4) * 8;

    float o[8][4];
#pragma unroll
    for (int j = 0; j < 8; j++)
#pragma unroll
        for (int u = 0; u < 4; u++) o[j][u] = 0.f;
    float m_r = -1e30f, m_r8 = -1e30f, l_r = 0.f, l_r8 = 0.f;
    float s[8][4];

    // QK of one tile: main f32 + corrections f16, combined into s
    auto qk_tile = [&](uint32_t stb_k) {
        uint32_t cqk[8][2];
#pragma unroll
        for (int j = 0; j < 8; j++) {
#pragma unroll
            for (int u = 0; u < 4; u++) s[j][u] = 0.f;
            cqk[j][0] = 0u; cqk[j][1] = 0u;
        }
#pragma unroll
        for (int ks = 0; ks < 4; ks++) {
#pragma unroll
            for (int jp = 0; jp < 4; jp++) {
                uint32_t rbase = stb_k + (uint32_t)((jp * 16 + k_r) * APK) * 2;
                uint32_t kh4[4], kl4[4];
                ldm_x4(kh4, rbase + (ks * 16 + k_c) * 2);
                ldm_x4(kl4, rbase + (64 + ks * 16 + k_c) * 2);
                mma_hf(s[2 * jp],     qf[ks], kh4 + 0);
                mma_hf(s[2 * jp + 1], qf[ks], kh4 + 2);
                mma_h2(cqk[2 * jp],     qf[4 + ks], kh4 + 0);
                mma_h2(cqk[2 * jp + 1], qf[4 + ks], kh4 + 2);
                mma_h2(cqk[2 * jp],     qf[ks],     kl4 + 0);
                mma_h2(cqk[2 * jp + 1], qf[ks],     kl4 + 2);
            }
        }
#pragma unroll
        for (int j = 0; j < 8; j++) {
            float2 c01 = unpack_h2(cqk[j][0]);
            float2 c23 = unpack_h2(cqk[j][1]);
            s[j][0] += c01.x; s[j][1] += c01.y;
            s[j][2] += c23.x; s[j][3] += c23.y;
        }
    };

    CP_WAIT(2);
    __syncthreads();
    qk_tile(sb + 0 * AS_B);

    for (int i = 0; i < 32; i++) {
        const int k0 = i * 64;

        float rmax = -1e30f, rmax8 = -1e30f;
#pragma unroll
        for (int j = 0; j < 8; j++) {
            const float* bp = bh + k0 + j * 8 + cq;
            s[j][0] += __ldg(bp);
            s[j][1] += __ldg(bp + 1);
            s[j][2] += __ldg(bp - 8);
            s[j][3] += __ldg(bp - 7);
            rmax  = fmaxf(rmax,  fmaxf(s[j][0], s[j][1]));
            rmax8 = fmaxf(rmax8, fmaxf(s[j][2], s[j][3]));
        }
#pragma unroll
        for (int off = 1; off <= 2; off <<= 1) {
            rmax  = fmaxf(rmax,  __shfl_xor_sync(0xffffffffu, rmax,  off));
            rmax8 = fmaxf(rmax8, __shfl_xor_sync(0xffffffffu, rmax8, off));
        }
        float mn  = fmaxf(m_r,  rmax);
        float mn8 = fmaxf(m_r8, rmax8);
        float cr  = __expf(m_r - mn);
        float cr8 = __expf(m_r8 - mn8);
        m_r = mn; m_r8 = mn8;
        float sum = 0.f, sum8 = 0.f;
#pragma unroll
        for (int j = 0; j < 8; j++) {
            s[j][0] = __expf(s[j][0] - mn);
            s[j][1] = __expf(s[j][1] - mn);
            s[j][2] = __expf(s[j][2] - mn8);
            s[j][3] = __expf(s[j][3] - mn8);
            sum  += s[j][0] + s[j][1];
            sum8 += s[j][2] + s[j][3];
        }
#pragma unroll
        for (int off = 1; off <= 2; off <<= 1) {
            sum  += __shfl_xor_sync(0xffffffffu, sum,  off);
            sum8 += __shfl_xor_sync(0xffffffffu, sum8, off);
        }
        l_r  = l_r  * cr  + sum;
        l_r8 = l_r8 * cr8 + sum8;
#pragma unroll
        for (int j = 0; j < 8; j++) {
            o[j][0] *= cr;  o[j][1] *= cr;
            o[j][2] *= cr8; o[j][3] *= cr8;
        }
        uint32_t pa[4][4];
#pragma unroll
        for (int ks = 0; ks < 4; ks++) {
            pa[ks][0] = pack_f16(s[2 * ks][0], s[2 * ks][1]);
            pa[ks][1] = pack_f16(s[2 * ks][2], s[2 * ks][3]);
            pa[ks][2] = pack_f16(s[2 * ks + 1][0], s[2 * ks + 1][1]);
            pa[ks][3] = pack_f16(s[2 * ks + 1][2], s[2 * ks + 1][3]);
        }

        const bool not_last = (i + 1 < 32);
        if (not_last) {
            if (i < 30) { CP_WAIT(1); } else { CP_WAIT(0); }
            __syncthreads();
            if (i + 3 < 32) issue_kv((i + 3) & 3, i + 3);
        }

        uint32_t stb_v = sb + (uint32_t)(i & 3) * AS_B;
        if (not_last)
            qk_tile(sb + (uint32_t)((i + 1) & 3) * AS_B);
#pragma unroll
        for (int ks = 0; ks < 4; ks++) {
#pragma unroll
            for (int jp = 0; jp < 4; jp++) {
                uint32_t v4[4];
                ldm_x4t(v4, stb_v + AK_B +
                            ((uint32_t)((ks * 16 + v_r) * APV + jp * 16 + v_c)) * 2);
                mma_hf(o[2 * jp],     pa[ks], v4 + 0);
                mma_hf(o[2 * jp + 1], pa[ks], v4 + 2);
            }
        }
    }

    // epilogue: ctx -> fp16 limb plane g_A2 [s][hi1024|lo1024]
    float ir = 1.f / l_r, ir8 = 1.f / l_r8;
#pragma unroll
    for (int j = 0; j < 8; j++) {
        int col = h * 64 + j * 8 + cq;
#pragma unroll
        for (int half_ = 0; half_ < 2; half_++) {
            int rr = q_r + half_ * 8;
            float scale = half_ ? ir8 : ir;
            float v0 = o[j][2 * half_ + 0] * scale;
            float v1 = o[j][2 * half_ + 1] * scale;
            __half h0 = __float2half_rn(v0), h1 = __float2half_rn(v1);
            __half* dst = g_A2 + (size_t)rr * KE + col;
            *(__half2*)dst = __halves2half2(h0, h1);
            *(__half2*)(dst + 1024) = __halves2half2(
                __float2half_rn(v0 - __half2float(h0)),
                __float2half_rn(v1 - __half2float(h1)));
        }
    }
}

// ---------------------------------------------------------------------------
extern "C" void kernel_launch(void* const* d_in, const int* in_sizes, int n_in,
                              void* d_out, int out_size) {
    const float* X   = (const float*)d_in[0];
    const float* Wq  = (const float*)d_in[1];
    const float* Wk  = (const float*)d_in[2];
    const float* Wv  = (const float*)d_in[3];
    const float* Wo  = (const float*)d_in[4];
    const float* rel = (const float*)d_in[5];
    float* out = (float*)d_out;

    const int gemm_smem = 3 * STAGE_B;      // 110592
    const int attn_smem = AS_N * AS_B;      // 106496
    cudaFuncSetAttribute(gemm_mma<true>,  cudaFuncAttributeMaxDynamicSharedMemorySize, gemm_smem);
    cudaFuncSetAttribute(gemm_mma<false>, cudaFuncAttributeMaxDynamicSharedMemorySize, gemm_smem);
    cudaFuncSetAttribute(attn_mma,        cudaFuncAttributeMaxDynamicSharedMemorySize, attn_smem);

    bias_kernel<<<(N_HEADS * 4095 + 255) / 256, 256>>>(rel);
    convA_kernel<<<(S_LEN * D_MODEL / 4) / 256, 256>>>(X);
    convB_kernel<<<dim3(32, 32, 4), dim3(32, 8)>>>(Wq, Wk, Wv, Wo);
    gemm_mma<true><<<dim3(24, 16), 256, gemm_smem>>>(nullptr);
    attn_mma<<<dim3(16, 16), 256, attn_smem>>>();
    gemm_mma<false><<<dim3(8, 16), 256, gemm_smem>>>(out);
}

// round 17
// speedup vs baseline: 2.4714x; 1.1789x over previous
#include <cuda_runtime.h>
#include <cuda_fp16.h>
#include <math.h>
#include <cstdint>

#define S_LEN 2048
#define D_MODEL 1024
#define N_HEADS 16
#define D_KV 64
#define KE 2048              // A limb-plane width [hi1024|lo1024]
#define HSQ (S_LEN * 128)    // per-head Q limb plane [Qh64|Ql64]
#define HSK (S_LEN * 64)     // per-head K / V planes

// ---------------- scratch (__device__ globals; no allocs) -------------------
__device__ float g_bias[N_HEADS * 4096];
__device__ __align__(16) __half g_A2[S_LEN * KE];        // X limbs, later ctx limbs
__device__ __align__(16) __half g_Bq[3072 * D_MODEL];    // Wq,Wk,Wv ^T fp16 (single plane)
__device__ __align__(16) __half g_Bo[1024 * D_MODEL];    // Wo^T fp16
__device__ __align__(16) __half g_Q2[N_HEADS * HSQ];     // [h][s][Qh64|Ql64]
__device__ __align__(16) __half g_K1[N_HEADS * HSK];     // [h][s][64] fp16
__device__ __align__(16) __half g_Vh[N_HEADS * HSK];     // V hi limb
__device__ __align__(16) __half g_Vl[N_HEADS * HSK];     // V lo limb

__device__ __forceinline__ uint32_t smem_u32(const void* p) {
    uint32_t a;
    asm("{ .reg .u64 t; cvta.to.shared.u64 t, %1; cvt.u32.u64 %0, t; }" : "=r"(a) : "l"(p));
    return a;
}

// ---------------- mma / ldmatrix / cp.async primitives ----------------------
__device__ __forceinline__ void ldm_x4(uint32_t* r, uint32_t addr) {
    asm volatile("ldmatrix.sync.aligned.m8n8.x4.shared.b16 {%0,%1,%2,%3}, [%4];"
                 : "=r"(r[0]), "=r"(r[1]), "=r"(r[2]), "=r"(r[3]) : "r"(addr));
}
__device__ __forceinline__ void ldm_x4t(uint32_t* r, uint32_t addr) {
    asm volatile("ldmatrix.sync.aligned.m8n8.x4.trans.shared.b16 {%0,%1,%2,%3}, [%4];"
                 : "=r"(r[0]), "=r"(r[1]), "=r"(r[2]), "=r"(r[3]) : "r"(addr));
}
__device__ __forceinline__ void mma_hf(float* d, const uint32_t* a, const uint32_t* b) {
    asm volatile("mma.sync.aligned.m16n8k16.row.col.f32.f16.f16.f32 "
                 "{%0,%1,%2,%3}, {%4,%5,%6,%7}, {%8,%9}, {%0,%1,%2,%3};"
                 : "+f"(d[0]), "+f"(d[1]), "+f"(d[2]), "+f"(d[3])
                 : "r"(a[0]), "r"(a[1]), "r"(a[2]), "r"(a[3]), "r"(b[0]), "r"(b[1]));
}
__device__ __forceinline__ void cp16(uint32_t saddr, const void* gaddr) {
    asm volatile("cp.async.cg.shared.global [%0], [%1], 16;" :: "r"(saddr), "l"(gaddr));
}
#define CP_COMMIT() asm volatile("cp.async.commit_group;" ::: "memory")
#define CP_WAIT(n)  asm volatile("cp.async.wait_group %0;" :: "n"(n) : "memory")

__device__ __forceinline__ uint32_t pack_f16(float lo, float hi) {
    uint32_t r;
    asm("cvt.rn.f16x2.f32 %0, %1, %2;" : "=r"(r) : "f"(hi), "f"(lo));
    return r;
}

// ---------------------------------------------------------------------------
// Bias LUT
// ---------------------------------------------------------------------------
__global__ void bias_kernel(const float* __restrict__ rel_bias) {
    int idx = blockIdx.x * blockDim.x + threadIdx.x;
    if (idx >= N_HEADS * 4095) return;
    int h = idx / 4095;
    int di = idx % 4095;
    int delta = di - 2047;
    int bucket = (delta > 0) ? 16 : 0;
    int rp = abs(delta);
    if (rp < 8) {
        bucket += rp;
    } else {
        float lr = logf((float)rp * 0.125f) / 2.7725887f;
        int large = 8 + (int)(lr * 8.0f);
        bucket += (large < 15) ? large : 15;
    }
    g_bias[h * 4096 + di] = rel_bias[bucket * N_HEADS + h];
}

// ---------------------------------------------------------------------------
// convA: X -> fp16 hi/lo limb plane (vectorized)
// ---------------------------------------------------------------------------
__global__ void convA_kernel(const float* __restrict__ X) {
    int i = (blockIdx.x * blockDim.x + threadIdx.x) * 4;
    int row = i >> 10, col = i & 1023;
    float4 v = *(const float4*)(X + i);
    float x[4] = {v.x, v.y, v.z, v.w};
    __half hi[4], lo[4];
#pragma unroll
    for (int u = 0; u < 4; u++) {
        hi[u] = __float2half_rn(x[u]);
        lo[u] = __float2half_rn(x[u] - __half2float(hi[u]));
    }
    __half* dst = g_A2 + (size_t)row * KE + col;
    *(__half2*)(dst + 0) = __halves2half2(hi[0], hi[1]);
    *(__half2*)(dst + 2) = __halves2half2(hi[2], hi[3]);
    *(__half2*)(dst + 1024) = __halves2half2(lo[0], lo[1]);
    *(__half2*)(dst + 1026) = __halves2half2(lo[2], lo[3]);
}

// convW: transpose + fp16 single-plane; z: 0=Wq 1=Wk 2=Wv -> g_Bq, 3=Wo -> g_Bo
__global__ void convW_kernel(const float* __restrict__ Wq, const float* __restrict__ Wk,
                             const float* __restrict__ Wv, const float* __restrict__ Wo) {
    const float* W = (blockIdx.z == 0) ? Wq : (blockIdx.z == 1) ? Wk
                   : (blockIdx.z == 2) ? Wv : Wo;
    __shared__ float sm[32][33];
    int n0 = blockIdx.x * 32, k0 = blockIdx.y * 32;
    int tx = threadIdx.x, ty = threadIdx.y;   // 32 x 8
#pragma unroll
    for (int j = 0; j < 4; j++)
        sm[ty + j * 8][tx] = W[(size_t)(k0 + ty + j * 8) * D_MODEL + n0 + tx];
    __syncthreads();
#pragma unroll
    for (int j = 0; j < 4; j++) {
        int n = n0 + ty + j * 8, k = k0 + tx;
        __half h = __float2half_rn(sm[tx][ty + j * 8]);
        if (blockIdx.z < 3)
            g_Bq[(size_t)(blockIdx.z * 1024 + n) * D_MODEL + k] = h;
        else
            g_Bo[(size_t)n * D_MODEL + k] = h;
    }
}

// ---------------------------------------------------------------------------
// fp16 GEMM, 2-product with B-fragment reuse: C = AhBh + AlBh (A exact 22-bit).
// 128x128 tile, BK=64, S=3 stages, one sync per kb.
// ---------------------------------------------------------------------------
#define PITCH 72                          // 64 + 8 (144B rows)
#define ARR_B (128 * PITCH * 2)           // 18432 B per array
#define STG_B (3 * ARR_B)                 // Ah, Al, B = 55296 B per stage

template <bool QKV>
__global__ __launch_bounds__(256) void gemm_mma(float* __restrict__ Cout) {
    extern __shared__ __align__(16) __half sm[];
    const int t = threadIdx.x;
    const int warp = t >> 5, lane = t & 31;
    const int m0 = blockIdx.y * 128, n0 = blockIdx.x * 128;
    const int wm0 = (warp >> 1) * 32;
    const int wn0 = (warp & 1) * 64;

    const __half* Bbase = (QKV ? g_Bq : g_Bo);
    const uint32_t sbase = smem_u32(sm);

    const int lr = t >> 3, lc = (t & 7) * 8;   // 32 rows x 8 chunks per pass

    auto issue_stage = [&](int slot, int kb) {
        uint32_t so = sbase + (uint32_t)slot * STG_B;
#pragma unroll
        for (int p = 0; p < 4; p++) {
            int row = lr + p * 32;
            uint32_t sofs = ((uint32_t)row * PITCH + lc) * 2;
            size_t ka = (size_t)kb * 64 + lc;
            cp16(so + sofs,             g_A2 + (size_t)(m0 + row) * KE + ka);          // Ah
            cp16(so + ARR_B + sofs,     g_A2 + (size_t)(m0 + row) * KE + 1024 + ka);   // Al
            cp16(so + 2 * ARR_B + sofs, Bbase + (size_t)(n0 + row) * D_MODEL + ka);    // B
        }
        CP_COMMIT();
    };

    float d[2][8][4];
#pragma unroll
    for (int i = 0; i < 2; i++)
#pragma unroll
        for (int j = 0; j < 8; j++)
#pragma unroll
            for (int u = 0; u < 4; u++) d[i][j][u] = 0.f;

    const int arow = wm0 + (lane & 15);
    const int acolq = (lane >> 4) * 8;
    const int brow2 = wn0 + (lane >> 4) * 8 + (lane & 7);
    const int bcol2 = ((lane >> 3) & 1) * 8;

    issue_stage(0, 0);
    issue_stage(1, 1);

    for (int kb = 0; kb < 16; kb++) {
        if (kb + 1 < 16) { CP_WAIT(1); } else { CP_WAIT(0); }
        __syncthreads();
        if (kb + 2 < 16) issue_stage((kb + 2) % 3, kb + 2);
        uint32_t so = sbase + (uint32_t)(kb % 3) * STG_B;
#pragma unroll
        for (int ks = 0; ks < 4; ks++) {
            uint32_t ah[2][4], al[2][4];
#pragma unroll
            for (int i = 0; i < 2; i++) {
                uint32_t aofs = ((uint32_t)(arow + i * 16) * PITCH + ks * 16 + acolq) * 2;
                ldm_x4(ah[i], so + aofs);
                ldm_x4(al[i], so + ARR_B + aofs);
            }
#pragma unroll
            for (int jp = 0; jp < 4; jp++) {
                uint32_t bh4[4];
                ldm_x4(bh4, so + 2 * ARR_B +
                            ((uint32_t)(brow2 + jp * 16) * PITCH + ks * 16 + bcol2) * 2);
                mma_hf(d[0][2 * jp],     ah[0], bh4 + 0);
                mma_hf(d[1][2 * jp],     ah[1], bh4 + 0);
                mma_hf(d[0][2 * jp + 1], ah[0], bh4 + 2);
                mma_hf(d[1][2 * jp + 1], ah[1], bh4 + 2);
                mma_hf(d[0][2 * jp],     al[0], bh4 + 0);
                mma_hf(d[1][2 * jp],     al[1], bh4 + 0);
                mma_hf(d[0][2 * jp + 1], al[0], bh4 + 2);
                mma_hf(d[1][2 * jp + 1], al[1], bh4 + 2);
            }
        }
    }

    // epilogue
#pragma unroll
    for (int i = 0; i < 2; i++) {
        int r = m0 + wm0 + i * 16 + (lane >> 2);
#pragma unroll
        for (int j = 0; j < 8; j++) {
            int n = n0 + wn0 + j * 8 + (lane & 3) * 2;
#pragma unroll
            for (int half_ = 0; half_ < 2; half_++) {
                int rr = r + half_ * 8;
                float v0 = d[i][j][2 * half_ + 0];
                float v1 = d[i][j][2 * half_ + 1];
                if (QKV) {
                    int z = n >> 10, hd = (n >> 6) & 15, dd = n & 63;
                    if (z == 0) {
                        __half* q = g_Q2 + (size_t)hd * HSQ + (size_t)rr * 128 + dd;
                        __half h0 = __float2half_rn(v0), h1 = __float2half_rn(v1);
                        *(__half2*)q = __halves2half2(h0, h1);
                        *(__half2*)(q + 64) = __halves2half2(
                            __float2half_rn(v0 - __half2float(h0)),
                            __float2half_rn(v1 - __half2float(h1)));
                    } else if (z == 1) {
                        __half* k = g_K1 + (size_t)hd * HSK + (size_t)rr * 64 + dd;
                        *(__half2*)k = __halves2half2(__float2half_rn(v0), __float2half_rn(v1));
                    } else {
                        __half h0 = __float2half_rn(v0), h1 = __float2half_rn(v1);
                        size_t o = (size_t)hd * HSK + (size_t)rr * 64 + dd;
                        *(__half2*)(g_Vh + o) = __halves2half2(h0, h1);
                        *(__half2*)(g_Vl + o) = __halves2half2(
                            __float2half_rn(v0 - __half2float(h0)),
                            __float2half_rn(v1 - __half2float(h1)));
                    }
                } else {
                    *(float2*)(Cout + (size_t)rr * D_MODEL + n) = make_float2(v0, v1);
                }
            }
        }
    }
}

// ---------------------------------------------------------------------------
// fp16 flash attention: S = (Qh+Ql)·Kh via kh-fragment reuse (2 products).
// P fp16; PV with V hi/lo limbs. 64-key tiles, S=4 stages, QK(i+1) || PV(i).
// ---------------------------------------------------------------------------
#define APQ 136                           // Q pitch (128+8)
#define APK 72                            // K/V pitch (64+8)
#define KV_K (64 * APK * 2)               // 9216 per array
#define AS_B (3 * KV_K)                   // K, Vh, Vl = 27648 per stage
#define AS_N 4

__global__ __launch_bounds__(256) void attn_mma() {
    extern __shared__ __align__(16) char smem[];
    const uint32_t sb = smem_u32(smem);
    const int t = threadIdx.x, w = t >> 5, lane = t & 31;
    const int h = blockIdx.y, q0 = blockIdx.x * 128;

    const __half* Q2 = g_Q2 + (size_t)h * HSQ;
    const __half* K1 = g_K1 + (size_t)h * HSK;
    const __half* Vh = g_Vh + (size_t)h * HSK;
    const __half* Vl = g_Vl + (size_t)h * HSK;

    // stage Q (128x128 halfs), extract fragments
    {
        int row = t >> 4, colc = (t & 15) * 8;
#pragma unroll
        for (int p = 0; p < 8; p++) {
            int r = row + p * 16;
            cp16(sb + ((uint32_t)r * APQ + colc) * 2, Q2 + (size_t)(q0 + r) * 128 + colc);
        }
        CP_COMMIT();
        CP_WAIT(0);
        __syncthreads();
    }
    uint32_t qf[8][4];   // 0-3: Qh chunks, 4-7: Ql chunks
    {
        int arow = w * 16 + (lane & 15);
        int acol = (lane >> 4) * 8;
#pragma unroll
        for (int ks = 0; ks < 8; ks++)
            ldm_x4(qf[ks], sb + ((uint32_t)arow * APQ + ks * 16 + acol) * 2);
    }
    __syncthreads();

    auto issue_kv = [&](int slot, int i) {
        int k0 = i * 64;
        uint32_t base = sb + (uint32_t)slot * AS_B;
        int row = t >> 2;
#pragma unroll
        for (int p = 0; p < 2; p++) {
            int colc = (t & 3) * 8 + p * 32;
            uint32_t so = ((uint32_t)row * APK + colc) * 2;
            size_t g = (size_t)(k0 + row) * 64 + colc;
            cp16(base + so,             K1 + g);
            cp16(base + KV_K + so,      Vh + g);
            cp16(base + 2 * KV_K + so,  Vl + g);
        }
        CP_COMMIT();
    };

    issue_kv(0, 0);
    issue_kv(1, 1);
    issue_kv(2, 2);

    const int cq = (lane & 3) * 2;
    const int q_r = q0 + w * 16 + (lane >> 2);
    const float* bh = g_bias + h * 4096 + 2047 - q_r;

    const int k_r = (lane >> 4) * 8 + (lane & 7);
    const int k_c = ((lane >> 3) & 1) * 8;
    const int v_r = (lane & 7) + ((lane >> 3) & 1) * 8;
    const int v_c = (lane >> 4) * 8;

    float o[8][4];
#pragma unroll
    for (int j = 0; j < 8; j++)
#pragma unroll
        for (int u = 0; u < 4; u++) o[j][u] = 0.f;
    float m_r = -1e30f, m_r8 = -1e30f, l_r = 0.f, l_r8 = 0.f;
    float s[8][4];

    // QK of one tile: kh fragments reused by Qh and Ql
    auto qk_tile = [&](uint32_t stb_k) {
#pragma unroll
        for (int j = 0; j < 8; j++)
#pragma unroll
            for (int u = 0; u < 4; u++) s[j][u] = 0.f;
#pragma unroll
        for (int ks = 0; ks < 4; ks++) {
#pragma unroll
            for (int jp = 0; jp < 4; jp++) {
                uint32_t kh4[4];
                ldm_x4(kh4, stb_k + ((uint32_t)((jp * 16 + k_r) * APK + ks * 16 + k_c)) * 2);
                mma_hf(s[2 * jp],     qf[ks],     kh4 + 0);
                mma_hf(s[2 * jp + 1], qf[ks],     kh4 + 2);
                mma_hf(s[2 * jp],     qf[4 + ks], kh4 + 0);
                mma_hf(s[2 * jp + 1], qf[4 + ks], kh4 + 2);
            }
        }
    };

    CP_WAIT(2);
    __syncthreads();
    qk_tile(sb + 0 * AS_B);

    for (int i = 0; i < 32; i++) {
        const int k0 = i * 64;

        // softmax(i)
        float rmax = -1e30f, rmax8 = -1e30f;
#pragma unroll
        for (int j = 0; j < 8; j++) {
            const float* bp = bh + k0 + j * 8 + cq;
            s[j][0] += __ldg(bp);
            s[j][1] += __ldg(bp + 1);
            s[j][2] += __ldg(bp - 8);
            s[j][3] += __ldg(bp - 7);
            rmax  = fmaxf(rmax,  fmaxf(s[j][0], s[j][1]));
            rmax8 = fmaxf(rmax8, fmaxf(s[j][2], s[j][3]));
        }
#pragma unroll
        for (int off = 1; off <= 2; off <<= 1) {
            rmax  = fmaxf(rmax,  __shfl_xor_sync(0xffffffffu, rmax,  off));
            rmax8 = fmaxf(rmax8, __shfl_xor_sync(0xffffffffu, rmax8, off));
        }
        float mn  = fmaxf(m_r,  rmax);
        float mn8 = fmaxf(m_r8, rmax8);
        float cr  = __expf(m_r - mn);
        float cr8 = __expf(m_r8 - mn8);
        m_r = mn; m_r8 = mn8;
        float sum = 0.f, sum8 = 0.f;
#pragma unroll
        for (int j = 0; j < 8; j++) {
            s[j][0] = __expf(s[j][0] - mn);
            s[j][1] = __expf(s[j][1] - mn);
            s[j][2] = __expf(s[j][2] - mn8);
            s[j][3] = __expf(s[j][3] - mn8);
            sum  += s[j][0] + s[j][1];
            sum8 += s[j][2] + s[j][3];
        }
#pragma unroll
        for (int off = 1; off <= 2; off <<= 1) {
            sum  += __shfl_xor_sync(0xffffffffu, sum,  off);
            sum8 += __shfl_xor_sync(0xffffffffu, sum8, off);
        }
        l_r  = l_r  * cr  + sum;
        l_r8 = l_r8 * cr8 + sum8;
#pragma unroll
        for (int j = 0; j < 8; j++) {
            o[j][0] *= cr;  o[j][1] *= cr;
            o[j][2] *= cr8; o[j][3] *= cr8;
        }
        uint32_t pa[4][4];
#pragma unroll
        for (int ks = 0; ks < 4; ks++) {
            pa[ks][0] = pack_f16(s[2 * ks][0], s[2 * ks][1]);
            pa[ks][1] = pack_f16(s[2 * ks][2], s[2 * ks][3]);
            pa[ks][2] = pack_f16(s[2 * ks + 1][0], s[2 * ks + 1][1]);
            pa[ks][3] = pack_f16(s[2 * ks + 1][2], s[2 * ks + 1][3]);
        }

        // barrier + stage i+3
        const bool not_last = (i + 1 < 32);
        if (not_last) {
            if (i < 30) { CP_WAIT(1); } else { CP_WAIT(0); }
            __syncthreads();
            if (i + 3 < 32) issue_kv((i + 3) & 3, i + 3);
        }

        // QK(i+1) interleaved with PV(i)
        uint32_t stb_v = sb + (uint32_t)(i & 3) * AS_B;
        if (not_last)
            qk_tile(sb + (uint32_t)((i + 1) & 3) * AS_B);
#pragma unroll
        for (int ks = 0; ks < 4; ks++) {
#pragma unroll
            for (int jp = 0; jp < 4; jp++) {
                uint32_t vofs = ((uint32_t)((ks * 16 + v_r) * APK + jp * 16 + v_c)) * 2;
                uint32_t vh4[4], vl4[4];
                ldm_x4t(vh4, stb_v + KV_K + vofs);
                ldm_x4t(vl4, stb_v + 2 * KV_K + vofs);
                mma_hf(o[2 * jp],     pa[ks], vh4 + 0);
                mma_hf(o[2 * jp + 1], pa[ks], vh4 + 2);
                mma_hf(o[2 * jp],     pa[ks], vl4 + 0);
                mma_hf(o[2 * jp + 1], pa[ks], vl4 + 2);
            }
        }
    }

    // epilogue: ctx -> fp16 limb plane g_A2 [s][hi1024|lo1024]
    float ir = 1.f / l_r, ir8 = 1.f / l_r8;
#pragma unroll
    for (int j = 0; j < 8; j++) {
        int col = h * 64 + j * 8 + cq;
#pragma unroll
        for (int half_ = 0; half_ < 2; half_++) {
            int rr = q_r + half_ * 8;
            float scale = half_ ? ir8 : ir;
            float v0 = o[j][2 * half_ + 0] * scale;
            float v1 = o[j][2 * half_ + 1] * scale;
            __half h0 = __float2half_rn(v0), h1 = __float2half_rn(v1);
            __half* dst = g_A2 + (size_t)rr * KE + col;
            *(__half2*)dst = __halves2half2(h0, h1);
            *(__half2*)(dst + 1024) = __halves2half2(
                __float2half_rn(v0 - __half2float(h0)),
                __float2half_rn(v1 - __half2float(h1)));
        }
    }
}

// ---------------------------------------------------------------------------
extern "C" void kernel_launch(void* const* d_in, const int* in_sizes, int n_in,
                              void* d_out, int out_size) {
    const float* X   = (const float*)d_in[0];
    const float* Wq  = (const float*)d_in[1];
    const float* Wk  = (const float*)d_in[2];
    const float* Wv  = (const float*)d_in[3];
    const float* Wo  = (const float*)d_in[4];
    const float* rel = (const float*)d_in[5];
    float* out = (float*)d_out;

    const int gemm_smem = 3 * STG_B;        // 165888
    const int attn_smem = AS_N * AS_B;      // 110592 (>= 34816 Q staging)
    cudaFuncSetAttribute(gemm_mma<true>,  cudaFuncAttributeMaxDynamicSharedMemorySize, gemm_smem);
    cudaFuncSetAttribute(gemm_mma<false>, cudaFuncAttributeMaxDynamicSharedMemorySize, gemm_smem);
    cudaFuncSetAttribute(attn_mma,        cudaFuncAttributeMaxDynamicSharedMemorySize, attn_smem);

    bias_kernel<<<(N_HEADS * 4095 + 255) / 256, 256>>>(rel);
    convA_kernel<<<(S_LEN * D_MODEL / 4) / 256, 256>>>(X);
    convW_kernel<<<dim3(32, 32, 4), dim3(32, 8)>>>(Wq, Wk, Wv, Wo);
    gemm_mma<true><<<dim3(24, 16), 256, gemm_smem>>>(nullptr);
    attn_mma<<<dim3(16, 16), 256, attn_smem>>>();
    gemm_mma<false><<<dim3(8, 16), 256, gemm_smem>>>(out);
}